// round 2
// baseline (speedup 1.0000x reference)
#include <cuda_runtime.h>
#include <cstdint>

#define N_TYPES 95
#define EMB 128
#define TILE 64

// Precomputed tables (device globals: no allocation allowed)
__device__ float    g_PT[N_TYPES * 256];   // [z][0:128]=emb@W1^T + b_dense, [z][128:256]=emb@W2^T
__device__ unsigned g_W3T[EMB * EMB];      // W3 transposed to [k][i], tf32 bit patterns

__device__ __forceinline__ float silu_f(float x) {
    return __fdividef(x, 1.0f + __expf(-x));
}
__device__ __forceinline__ unsigned to_tf32(float x) {
    unsigned u; asm("cvt.rna.tf32.f32 %0, %1;" : "=r"(u) : "f"(x)); return u;
}
__device__ __forceinline__ void mma_tf32(float c[4],
                                         unsigned a0, unsigned a1, unsigned a2, unsigned a3,
                                         unsigned b0, unsigned b1) {
    asm volatile(
        "mma.sync.aligned.m16n8k8.row.col.f32.tf32.tf32.f32 "
        "{%0,%1,%2,%3}, {%4,%5,%6,%7}, {%8,%9}, {%0,%1,%2,%3};"
        : "+f"(c[0]), "+f"(c[1]), "+f"(c[2]), "+f"(c[3])
        : "r"(a0), "r"(a1), "r"(a2), "r"(a3), "r"(b0), "r"(b1));
}

// ---------------------------------------------------------------------------
// Precompute: PT[95][256] (node GEMM collapsed over atom types) + W3 transpose
// ---------------------------------------------------------------------------
__global__ void precompute_kernel(const float* __restrict__ emb,
                                  const float* __restrict__ Wd,
                                  const float* __restrict__ bd) {
    int b = blockIdx.x, t = threadIdx.x;
    if (b < N_TYPES) {
        __shared__ float er[EMB];
        if (t < EMB) er[t] = emb[b * EMB + t];
        __syncthreads();
        int i = t & 127, half = t >> 7;
        const float4* w4 = (const float4*)(Wd + (size_t)i * 384 + half * 128);
        float acc = (half == 0) ? bd[i] : 0.0f;   // fold b_dense into PT1
        #pragma unroll
        for (int k4 = 0; k4 < 32; k4++) {
            float4 w = w4[k4];
            acc += er[k4*4+0]*w.x + er[k4*4+1]*w.y + er[k4*4+2]*w.z + er[k4*4+3]*w.w;
        }
        g_PT[b * 256 + half * 128 + i] = acc;
    } else {
        int idx = (b - N_TYPES) * 256 + t;        // 0..16383
        int k = idx >> 7, i = idx & 127;
        g_W3T[idx] = to_tf32(Wd[(size_t)i * 384 + 256 + k]);
    }
}

// ---------------------------------------------------------------------------
// Main fused kernel: persistent CTAs (2 per SM), 64-edge tiles.
// Warp w (0..7): M-tile m = w>>1 (rows 16m..16m+15), N-half h = w&1 (64 cols).
// SMEM: W3 tf32 (stride 136, conflict-free), rbf tile, W_rbf, b_rbf, z gathers.
// PT table read from global (L1-resident, 95 hot rows).
// ---------------------------------------------------------------------------
#define W3S_WORDS   (128 * 136)        // 17408
#define SMEM_WORDS  (W3S_WORDS + TILE*6 + 768 + 128 + 2*TILE)  // 18816
#define SMEM_BYTES  (SMEM_WORDS * 4)   // 75264

__global__ void __launch_bounds__(256, 2) main_kernel(
    const int* __restrict__ Z, const int* __restrict__ src, const int* __restrict__ dst,
    const float* __restrict__ rbf, const float* __restrict__ dvec,
    const float* __restrict__ Wr, const float* __restrict__ brbf,
    float* __restrict__ out, int E, int nTiles)
{
    extern __shared__ unsigned sm[];
    unsigned* W3s    = sm;
    float*    rbf_s  = (float*)(sm + W3S_WORDS);
    float*    Wr_s   = rbf_s + TILE * 6;
    float*    brbf_s = Wr_s + 768;
    int*      zs_s   = (int*)(brbf_s + 128);
    int*      zd_s   = zs_s + TILE;

    int tid = threadIdx.x;
    for (int idx = tid; idx < EMB * EMB; idx += 256)
        W3s[(idx >> 7) * 136 + (idx & 127)] = g_W3T[idx];
    for (int idx = tid; idx < 768; idx += 256) Wr_s[idx] = Wr[idx];
    if (tid < 128) brbf_s[tid] = brbf[tid];

    int lane = tid & 31, w = tid >> 5;
    int g = lane >> 2, q = lane & 3;
    int m = w >> 1, h = w & 1;
    int r0 = m * 16 + g;                 // row within 64-edge tile
    int colb = h * 64;                   // this warp's column half
    size_t envBase = (size_t)E * EMB;

    for (int tile = blockIdx.x; tile < nTiles; tile += gridDim.x) {
        int base = tile * TILE;
        __syncthreads();   // previous tile's smem readers done before refill

        if (tid < TILE) {
            int e = base + tid; if (e >= E) e = E - 1;
            zs_s[tid] = Z[src[e]];
            zd_s[tid] = Z[dst[e]];
        } else if (tid < 2 * TILE) {
            // envelope * bessel branch (independent of smem)
            int e = base + (tid - TILE);
            if (e < E) {
                float x = dvec[e] * 0.2f;              // d / CUTOFF
                float inv = 1.0f / x;
                float x2 = x*x, x4 = x2*x2, x5 = x4*x, x6 = x5*x, x7 = x6*x;
                float env = inv - 28.0f*x5 + 48.0f*x6 - 21.0f*x7;   // p = 6
                float s = env * inv;                   // env(x) * (1/x)
                float* o = out + envBase + (size_t)e * 6;
                const float PIf = 3.14159265358979323846f;
                #pragma unroll
                for (int n = 1; n <= 6; n++) o[n - 1] = s * __sinf(((float)n * PIf) * x);
            }
        }
        {
            int lim = E * 6 - base * 6;
            for (int idx = tid; idx < TILE * 6; idx += 256)
                rbf_s[idx] = (idx < lim) ? rbf[base * 6 + idx] : 0.0f;
        }
        __syncthreads();

        float rb0[6], rb1[6];
        #pragma unroll
        for (int j = 0; j < 6; j++) {
            rb0[j] = rbf_s[r0 * 6 + j];
            rb1[j] = rbf_s[(r0 + 8) * 6 + j];
        }

        float c[8][4];
        #pragma unroll
        for (int nt = 0; nt < 8; nt++) { c[nt][0]=0.f; c[nt][1]=0.f; c[nt][2]=0.f; c[nt][3]=0.f; }

        // K loop: A-fragment (H = silu(rbf@Wr^T + b)) computed on the fly in
        // registers; B-fragments from conflict-free padded smem.
        #pragma unroll 2
        for (int k = 0; k < 16; k++) {
            int ca = 8 * k + q;
            const float* wA = Wr_s + ca * 6;
            float pa0 = brbf_s[ca],     pa1 = pa0;
            float pb0 = brbf_s[ca + 4], pb1 = pb0;
            #pragma unroll
            for (int j = 0; j < 6; j++) {
                float wa = wA[j], wb = wA[24 + j];
                pa0 += rb0[j] * wa;  pa1 += rb1[j] * wa;
                pb0 += rb0[j] * wb;  pb1 += rb1[j] * wb;
            }
            unsigned a0 = to_tf32(silu_f(pa0));
            unsigned a1 = to_tf32(silu_f(pa1));
            unsigned a2 = to_tf32(silu_f(pb0));
            unsigned a3 = to_tf32(silu_f(pb1));
            const unsigned* B0 = W3s + (8 * k + q) * 136 + colb + g;
            #pragma unroll
            for (int nt = 0; nt < 8; nt++)
                mma_tf32(c[nt], a0, a1, a2, a3, B0[nt * 8], B0[544 + nt * 8]); // 544 = 4*136
        }

        // epilogue: + PT1[Z[src]] + PT2[Z[dst]] (b_dense folded in), silu, store.
        // PT rows from global — 95 hot rows, L1-resident.
        int e0 = base + r0, e1 = e0 + 8;
        const float* p1a = g_PT + zs_s[r0] * 256;
        const float* p2a = g_PT + zd_s[r0] * 256 + 128;
        const float* p1b = g_PT + zs_s[r0 + 8] * 256;
        const float* p2b = g_PT + zd_s[r0 + 8] * 256 + 128;
        float* o0 = out + (size_t)e0 * EMB;
        float* o1 = out + (size_t)e1 * EMB;
        bool st0 = (e0 < E), st1 = (e1 < E);
        #pragma unroll
        for (int nt = 0; nt < 8; nt++) {
            int col = colb + nt * 8 + q * 2;
            float2 A1 = __ldg((const float2*)(p1a + col));
            float2 A2 = __ldg((const float2*)(p2a + col));
            float2 B1 = __ldg((const float2*)(p1b + col));
            float2 B2 = __ldg((const float2*)(p2b + col));
            float2 v0, v1;
            v0.x = silu_f(c[nt][0] + A1.x + A2.x);
            v0.y = silu_f(c[nt][1] + A1.y + A2.y);
            v1.x = silu_f(c[nt][2] + B1.x + B2.x);
            v1.y = silu_f(c[nt][3] + B1.y + B2.y);
            if (st0) *(float2*)(o0 + col) = v0;
            if (st1) *(float2*)(o1 + col) = v1;
        }
    }
}

extern "C" void kernel_launch(void* const* d_in, const int* in_sizes, int n_in,
                              void* d_out, int out_size) {
    const int*   Z    = (const int*)d_in[0];
    const int*   src  = (const int*)d_in[1];
    const int*   dst  = (const int*)d_in[2];
    const float* rbf  = (const float*)d_in[3];
    const float* d    = (const float*)d_in[4];
    const float* emb  = (const float*)d_in[5];
    const float* Wr   = (const float*)d_in[6];
    const float* brbf = (const float*)d_in[7];
    const float* Wd   = (const float*)d_in[8];
    const float* bd   = (const float*)d_in[9];
    int E = in_sizes[1];
    int nTiles = (E + TILE - 1) / TILE;

    precompute_kernel<<<N_TYPES + 64, 256>>>(emb, Wd, bd);

    cudaFuncSetAttribute(main_kernel, cudaFuncAttributeMaxDynamicSharedMemorySize, SMEM_BYTES);
    int dev = 0, nsm = 148;
    cudaGetDevice(&dev);
    cudaDeviceGetAttribute(&nsm, cudaDevAttrMultiProcessorCount, dev);

    main_kernel<<<2 * nsm, 256, SMEM_BYTES>>>(Z, src, dst, rbf, d, Wr, brbf,
                                              (float*)d_out, E, nTiles);
}

// round 3
// speedup vs baseline: 1.3746x; 1.3746x over previous
#include <cuda_runtime.h>
#include <cstdint>

#define N_TYPES 95

// Precomputed constants (device globals: no allocation allowed)
__device__ float    g_PT[N_TYPES * 256];   // [z][0:128]=emb@W1^T+b_dense, [z][128:256]=emb@W2^T
__device__ unsigned g_W3F[16384];          // W3 (tf32) pre-packed in mma B-fragment order

__device__ __forceinline__ float silu_f(float x) {
    return __fdividef(x, 1.0f + __expf(-x));
}
__device__ __forceinline__ unsigned to_tf32(float x) {
    unsigned u; asm("cvt.rna.tf32.f32 %0, %1;" : "=r"(u) : "f"(x)); return u;
}
__device__ __forceinline__ unsigned pack_bf16(float hi, float lo) {
    unsigned r; asm("cvt.rn.bf16x2.f32 %0, %1, %2;" : "=r"(r) : "f"(hi), "f"(lo)); return r;
}
__device__ __forceinline__ void mma_tf32(float c[4],
                                         unsigned a0, unsigned a1, unsigned a2, unsigned a3,
                                         unsigned b0, unsigned b1) {
    asm volatile(
        "mma.sync.aligned.m16n8k8.row.col.f32.tf32.tf32.f32 "
        "{%0,%1,%2,%3}, {%4,%5,%6,%7}, {%8,%9}, {%0,%1,%2,%3};"
        : "+f"(c[0]), "+f"(c[1]), "+f"(c[2]), "+f"(c[3])
        : "r"(a0), "r"(a1), "r"(a2), "r"(a3), "r"(b0), "r"(b1));
}

// ---------------------------------------------------------------------------
// Precompute: PT[95][256] (node GEMM collapsed over atom types) + W3 fragments
// Blocks 0..94: PT rows.  Blocks 95..158: W3F (fragment-ordered tf32).
// Fragment layout: uint4 index (k*8 + ntgp)*32 + lane holds, for lane (g,q):
//   .x = W3[col=2ntgp*8+g][k*8+q]      .y = W3[same col][k*8+q+4]
//   .z = W3[col=(2ntgp+1)*8+g][k*8+q]  .w = W3[same col][k*8+q+4]
// ---------------------------------------------------------------------------
__global__ void precompute_kernel(const float* __restrict__ emb,
                                  const float* __restrict__ Wd,
                                  const float* __restrict__ bd) {
    int b = blockIdx.x, t = threadIdx.x;
    if (b < N_TYPES) {
        __shared__ float er[128];
        if (t < 128) er[t] = emb[b * 128 + t];
        __syncthreads();
        int i = t & 127, half = t >> 7;
        const float4* w4 = (const float4*)(Wd + (size_t)i * 384 + half * 128);
        float acc = (half == 0) ? bd[i] : 0.0f;   // fold b_dense into PT1
        #pragma unroll
        for (int k4 = 0; k4 < 32; k4++) {
            float4 w = w4[k4];
            acc += er[k4*4+0]*w.x + er[k4*4+1]*w.y + er[k4*4+2]*w.z + er[k4*4+3]*w.w;
        }
        g_PT[b * 256 + half * 128 + i] = acc;
    } else {
        int idx  = (b - N_TYPES) * 256 + t;   // 0..16383
        int s    = idx & 3;
        int lane = (idx >> 2) & 31;
        int kgrp = idx >> 7;                  // 0..127 = k*8 + ntgp
        int k    = kgrp >> 3, ntgp = kgrp & 7;
        int ntg  = ntgp * 2 + (s >> 1);
        int bsel = s & 1;
        int col  = ntg * 8 + (lane >> 2);
        int kk   = k * 8 + (lane & 3) + bsel * 4;
        g_W3F[idx] = to_tf32(Wd[(size_t)col * 384 + 256 + kk]);
    }
}

// ---------------------------------------------------------------------------
// Main fused kernel: persistent CTAs (1/SM), 128-edge tiles, 3 phases:
//  fill (z/rbf/bessel) -> phase A (H=silu(rbf@Wr^T+b) once into bf16-fragment
//  smem) -> phase B (tf32 mma, vectorized LDS) + epilogue (PT add, silu, STG).
// ---------------------------------------------------------------------------
#define BF_WORDS 16384
#define HF_WORDS 8192
#define PT_WORDS (N_TYPES * 258)   // 24510, stride 258 avoids conflicts
#define SMEM_WORDS (BF_WORDS + HF_WORDS + PT_WORDS + 768 + 768 + 128 + 256)
#define SMEM_BYTES (SMEM_WORDS * 4)   // 204024

__global__ void __launch_bounds__(256, 1) main_kernel(
    const int* __restrict__ Z, const int* __restrict__ src, const int* __restrict__ dst,
    const float* __restrict__ rbf, const float* __restrict__ dvec,
    const float* __restrict__ Wr, const float* __restrict__ brbf,
    float* __restrict__ out, int E, int nTiles)
{
    extern __shared__ unsigned sm[];
    unsigned* BFs   = sm;
    uint2*    HFb   = (uint2*)(sm + BF_WORDS);
    float*    PTs   = (float*)(sm + BF_WORDS + HF_WORDS);
    float*    rbf_s = PTs + PT_WORDS;
    float*    Wr_s  = rbf_s + 768;
    float*    brbf_s= Wr_s + 768;
    int*      zs_s  = (int*)(brbf_s + 128);
    int*      zd_s  = zs_s + 128;

    int tid = threadIdx.x;
    for (int i = tid; i < BF_WORDS; i += 256) BFs[i] = g_W3F[i];
    for (int i = tid; i < N_TYPES * 256; i += 256)
        PTs[(i >> 8) * 258 + (i & 255)] = g_PT[i];
    for (int i = tid; i < 768; i += 256) Wr_s[i] = Wr[i];
    if (tid < 128) brbf_s[tid] = brbf[tid];

    int lane = tid & 31, w = tid >> 5;
    int g = lane >> 2, q = lane & 3;
    int mg = w >> 1, h = w & 1;          // phase B: rows 32*mg, col half h
    int rA0 = w * 16 + g;                // phase A: this thread's two rows
    size_t envBase = (size_t)E * 128;
    const uint4* BF4 = (const uint4*)BFs;

    for (int tile = blockIdx.x; tile < nTiles; tile += gridDim.x) {
        int base = tile * 128;
        __syncthreads();   // previous tile's readers done before refill

        if (tid < 128) {
            int e = base + tid; if (e >= E) e = E - 1;
            zs_s[tid] = Z[src[e]];
            zd_s[tid] = Z[dst[e]];
        } else {
            int e = base + (tid - 128);
            if (e < E) {   // envelope * bessel branch
                float x = dvec[e] * 0.2f;              // d / CUTOFF
                float inv = 1.0f / x;
                float x2 = x*x, x4 = x2*x2, x5 = x4*x, x6 = x5*x, x7 = x6*x;
                float env = inv - 28.0f*x5 + 48.0f*x6 - 21.0f*x7;   // p = 6
                float s = env * inv;
                float* o = out + envBase + (size_t)e * 6;
                const float PIf = 3.14159265358979323846f;
                #pragma unroll
                for (int n = 1; n <= 6; n++) o[n - 1] = s * __sinf(((float)n * PIf) * x);
            }
        }
        {
            int lim = E * 6 - base * 6;
            for (int idx = tid; idx < 768; idx += 256)
                rbf_s[idx] = (idx < lim) ? rbf[base * 6 + idx] : 0.0f;
        }
        __syncthreads();

        // ---- Phase A: H fragments (each H value computed exactly once) ----
        float rbA[6], rbB[6];
        #pragma unroll
        for (int j = 0; j < 6; j++) {
            rbA[j] = rbf_s[rA0 * 6 + j];
            rbB[j] = rbf_s[(rA0 + 8) * 6 + j];
        }
        #pragma unroll 2
        for (int k = 0; k < 16; k++) {
            int ca = 8 * k + q;
            const float* wA = Wr_s + ca * 6;
            float pa0 = brbf_s[ca],     pa1 = pa0;
            float pb0 = brbf_s[ca + 4], pb1 = pb0;
            #pragma unroll
            for (int j = 0; j < 6; j++) {
                float wa = wA[j], wb = wA[24 + j];
                pa0 += rbA[j] * wa;  pa1 += rbB[j] * wa;
                pb0 += rbA[j] * wb;  pb1 += rbB[j] * wb;
            }
            uint2 v;
            v.x = pack_bf16(silu_f(pa1), silu_f(pa0));   // hi=a1(row+8), lo=a0
            v.y = pack_bf16(silu_f(pb1), silu_f(pb0));   // hi=a3,        lo=a2
            HFb[(w * 16 + k) * 32 + lane] = v;
        }
        __syncthreads();

        // ---- Phase B: 32x64 warp tile, B via LDS.128, A via LDS.64 ----
        float c[2][8][4];
        #pragma unroll
        for (int mtl = 0; mtl < 2; mtl++)
            #pragma unroll
            for (int nt = 0; nt < 8; nt++)
                { c[mtl][nt][0]=0.f; c[mtl][nt][1]=0.f; c[mtl][nt][2]=0.f; c[mtl][nt][3]=0.f; }

        #pragma unroll 4
        for (int k = 0; k < 16; k++) {
            int bb = (k * 8 + h * 4) * 32 + lane;
            uint4 b0 = BF4[bb], b1 = BF4[bb + 32], b2 = BF4[bb + 64], b3 = BF4[bb + 96];
            uint2 A0 = HFb[((2 * mg)     * 16 + k) * 32 + lane];
            uint2 A1 = HFb[((2 * mg + 1) * 16 + k) * 32 + lane];
            unsigned a00 = A0.x << 16, a01 = A0.x & 0xFFFF0000u;
            unsigned a02 = A0.y << 16, a03 = A0.y & 0xFFFF0000u;
            unsigned a10 = A1.x << 16, a11 = A1.x & 0xFFFF0000u;
            unsigned a12 = A1.y << 16, a13 = A1.y & 0xFFFF0000u;
            mma_tf32(c[0][0], a00,a01,a02,a03, b0.x, b0.y);
            mma_tf32(c[0][1], a00,a01,a02,a03, b0.z, b0.w);
            mma_tf32(c[0][2], a00,a01,a02,a03, b1.x, b1.y);
            mma_tf32(c[0][3], a00,a01,a02,a03, b1.z, b1.w);
            mma_tf32(c[0][4], a00,a01,a02,a03, b2.x, b2.y);
            mma_tf32(c[0][5], a00,a01,a02,a03, b2.z, b2.w);
            mma_tf32(c[0][6], a00,a01,a02,a03, b3.x, b3.y);
            mma_tf32(c[0][7], a00,a01,a02,a03, b3.z, b3.w);
            mma_tf32(c[1][0], a10,a11,a12,a13, b0.x, b0.y);
            mma_tf32(c[1][1], a10,a11,a12,a13, b0.z, b0.w);
            mma_tf32(c[1][2], a10,a11,a12,a13, b1.x, b1.y);
            mma_tf32(c[1][3], a10,a11,a12,a13, b1.z, b1.w);
            mma_tf32(c[1][4], a10,a11,a12,a13, b2.x, b2.y);
            mma_tf32(c[1][5], a10,a11,a12,a13, b2.z, b2.w);
            mma_tf32(c[1][6], a10,a11,a12,a13, b3.x, b3.y);
            mma_tf32(c[1][7], a10,a11,a12,a13, b3.z, b3.w);
        }

        // ---- epilogue: + PT1[Z[src]] + PT2[Z[dst]], silu, store ----
        #pragma unroll
        for (int mtl = 0; mtl < 2; mtl++) {
            int r = (2 * mg + mtl) * 16 + g;
            int e0 = base + r, e1 = e0 + 8;
            const float* p1a = PTs + zs_s[r] * 258;
            const float* p2a = PTs + zd_s[r] * 258 + 128;
            const float* p1b = PTs + zs_s[r + 8] * 258;
            const float* p2b = PTs + zd_s[r + 8] * 258 + 128;
            float* o0 = out + (size_t)e0 * 128;
            float* o1 = out + (size_t)e1 * 128;
            bool st0 = (e0 < E), st1 = (e1 < E);
            #pragma unroll
            for (int nt = 0; nt < 8; nt++) {
                int col = h * 64 + nt * 8 + q * 2;
                float2 A1v = *(const float2*)(p1a + col);
                float2 A2v = *(const float2*)(p2a + col);
                float2 B1v = *(const float2*)(p1b + col);
                float2 B2v = *(const float2*)(p2b + col);
                float2 v0, v1;
                v0.x = silu_f(c[mtl][nt][0] + A1v.x + A2v.x);
                v0.y = silu_f(c[mtl][nt][1] + A1v.y + A2v.y);
                v1.x = silu_f(c[mtl][nt][2] + B1v.x + B2v.x);
                v1.y = silu_f(c[mtl][nt][3] + B1v.y + B2v.y);
                if (st0) *(float2*)(o0 + col) = v0;
                if (st1) *(float2*)(o1 + col) = v1;
            }
        }
    }
}

extern "C" void kernel_launch(void* const* d_in, const int* in_sizes, int n_in,
                              void* d_out, int out_size) {
    const int*   Z    = (const int*)d_in[0];
    const int*   src  = (const int*)d_in[1];
    const int*   dst  = (const int*)d_in[2];
    const float* rbf  = (const float*)d_in[3];
    const float* d    = (const float*)d_in[4];
    const float* emb  = (const float*)d_in[5];
    const float* Wr   = (const float*)d_in[6];
    const float* brbf = (const float*)d_in[7];
    const float* Wd   = (const float*)d_in[8];
    const float* bd   = (const float*)d_in[9];
    int E = in_sizes[1];
    int nTiles = (E + 127) / 128;

    precompute_kernel<<<N_TYPES + 64, 256>>>(emb, Wd, bd);

    cudaFuncSetAttribute(main_kernel, cudaFuncAttributeMaxDynamicSharedMemorySize, SMEM_BYTES);
    int dev = 0, nsm = 148;
    cudaGetDevice(&dev);
    cudaDeviceGetAttribute(&nsm, cudaDevAttrMultiProcessorCount, dev);

    main_kernel<<<nsm, 256, SMEM_BYTES>>>(Z, src, dst, rbf, d, Wr, brbf,
                                          (float*)d_out, E, nTiles);
}

// round 4
// speedup vs baseline: 1.5879x; 1.1552x over previous
#include <cuda_runtime.h>
#include <cstdint>

#define N_TYPES 95

// Precomputed constants (device globals: no allocation allowed)
__device__ float    g_PT[N_TYPES * 256];   // [z][0:128]=emb@W1^T+b_dense, [z][128:256]=emb@W2^T
__device__ unsigned g_W3F[16384];          // W3 (tf32) pre-packed in mma B-fragment order

__device__ __forceinline__ float silu_f(float x) {
    return __fdividef(x, 1.0f + __expf(-x));
}
__device__ __forceinline__ unsigned to_tf32(float x) {
    unsigned u; asm("cvt.rna.tf32.f32 %0, %1;" : "=r"(u) : "f"(x)); return u;
}
__device__ __forceinline__ unsigned pack_bf16(float hi, float lo) {
    unsigned r; asm("cvt.rn.bf16x2.f32 %0, %1, %2;" : "=r"(r) : "f"(hi), "f"(lo)); return r;
}
__device__ __forceinline__ void mma_tf32(float c[4],
                                         unsigned a0, unsigned a1, unsigned a2, unsigned a3,
                                         unsigned b0, unsigned b1) {
    asm volatile(
        "mma.sync.aligned.m16n8k8.row.col.f32.tf32.tf32.f32 "
        "{%0,%1,%2,%3}, {%4,%5,%6,%7}, {%8,%9}, {%0,%1,%2,%3};"
        : "+f"(c[0]), "+f"(c[1]), "+f"(c[2]), "+f"(c[3])
        : "r"(a0), "r"(a1), "r"(a2), "r"(a3), "r"(b0), "r"(b1));
}

// ---------------------------------------------------------------------------
// Precompute: PT[95][256] (node GEMM collapsed over atom types) + W3 fragments
// Fragment layout: uint4 index (k*8 + ntgp)*32 + lane holds, for lane (g,q):
//   .x = W3[col=2ntgp*8+g][k*8+q]      .y = W3[same col][k*8+q+4]
//   .z = W3[col=(2ntgp+1)*8+g][k*8+q]  .w = W3[same col][k*8+q+4]
// ---------------------------------------------------------------------------
__global__ void precompute_kernel(const float* __restrict__ emb,
                                  const float* __restrict__ Wd,
                                  const float* __restrict__ bd) {
    int b = blockIdx.x, t = threadIdx.x;
    if (b < N_TYPES) {
        __shared__ float er[128];
        if (t < 128) er[t] = emb[b * 128 + t];
        __syncthreads();
        int i = t & 127, half = t >> 7;
        const float4* w4 = (const float4*)(Wd + (size_t)i * 384 + half * 128);
        float acc = (half == 0) ? bd[i] : 0.0f;   // fold b_dense into PT1
        #pragma unroll
        for (int k4 = 0; k4 < 32; k4++) {
            float4 w = w4[k4];
            acc += er[k4*4+0]*w.x + er[k4*4+1]*w.y + er[k4*4+2]*w.z + er[k4*4+3]*w.w;
        }
        g_PT[b * 256 + half * 128 + i] = acc;
    } else {
        int idx  = (b - N_TYPES) * 256 + t;   // 0..16383
        int s    = idx & 3;
        int lane = (idx >> 2) & 31;
        int kgrp = idx >> 7;                  // 0..127 = k*8 + ntgp
        int k    = kgrp >> 3, ntgp = kgrp & 7;
        int ntg  = ntgp * 2 + (s >> 1);
        int bsel = s & 1;
        int col  = ntg * 8 + (lane >> 2);
        int kk   = k * 8 + (lane & 3) + bsel * 4;
        g_W3F[idx] = to_tf32(Wd[(size_t)col * 384 + 256 + kk]);
    }
}

// ---------------------------------------------------------------------------
// Main fused kernel: persistent CTAs (1/SM), 512 threads (16 warps), 128-edge
// tiles, 3 phases: fill -> phase A (H=silu(rbf@Wr^T+b) once, bf16 fragments)
// -> phase B (tf32 mma, 16x64 warp tiles) + epilogue (PT add, silu, STG).
// ---------------------------------------------------------------------------
#define BF_WORDS 16384
#define HF_WORDS 8192
#define PT_WORDS (N_TYPES * 258)   // 24510, stride 258 avoids conflicts
#define SMEM_WORDS (BF_WORDS + HF_WORDS + PT_WORDS + 768 + 768 + 128 + 256)
#define SMEM_BYTES (SMEM_WORDS * 4)   // 204024

__global__ void __launch_bounds__(512, 1) main_kernel(
    const int* __restrict__ Z, const int* __restrict__ src, const int* __restrict__ dst,
    const float* __restrict__ rbf, const float* __restrict__ dvec,
    const float* __restrict__ Wr, const float* __restrict__ brbf,
    float* __restrict__ out, int E, int nTiles)
{
    extern __shared__ unsigned sm[];
    unsigned* BFs   = sm;
    uint2*    HFb   = (uint2*)(sm + BF_WORDS);
    float*    PTs   = (float*)(sm + BF_WORDS + HF_WORDS);
    float*    rbf_s = PTs + PT_WORDS;
    float*    Wr_s  = rbf_s + 768;
    float*    brbf_s= Wr_s + 768;
    int*      zs_s  = (int*)(brbf_s + 128);
    int*      zd_s  = zs_s + 128;

    int tid = threadIdx.x;
    for (int i = tid; i < BF_WORDS; i += 512) BFs[i] = g_W3F[i];
    for (int i = tid; i < N_TYPES * 256; i += 512)
        PTs[(i >> 8) * 258 + (i & 255)] = g_PT[i];
    for (int i = tid; i < 768; i += 512) Wr_s[i] = Wr[i];
    if (tid < 128) brbf_s[tid] = brbf[tid];

    int lane = tid & 31, w = tid >> 5;
    int g = lane >> 2, q = lane & 3;
    // phase A: row-group rgA = w&7, k-range start kA = (w>>3)*8
    int rgA = w & 7, kA = (w >> 3) * 8;
    int rA0 = rgA * 16 + g;
    // phase B: m = w>>1 (rows 16m..16m+15), h = w&1 (64-col half)
    int m = w >> 1, h = w & 1;
    int rB0 = m * 16 + g;
    size_t envBase = (size_t)E * 128;
    const uint4* BF4 = (const uint4*)BFs;

    for (int tile = blockIdx.x; tile < nTiles; tile += gridDim.x) {
        int base = tile * 128;
        __syncthreads();   // previous tile's readers done before refill

        if (tid < 128) {
            int e = base + tid; if (e >= E) e = E - 1;
            zs_s[tid] = Z[src[e]];
            zd_s[tid] = Z[dst[e]];
        } else if (tid < 256) {
            int e = base + (tid - 128);
            if (e < E) {   // envelope * bessel branch
                float x = dvec[e] * 0.2f;              // d / CUTOFF
                float inv = 1.0f / x;
                float x2 = x*x, x4 = x2*x2, x5 = x4*x, x6 = x5*x, x7 = x6*x;
                float env = inv - 28.0f*x5 + 48.0f*x6 - 21.0f*x7;   // p = 6
                float s = env * inv;
                float* o = out + envBase + (size_t)e * 6;
                const float PIf = 3.14159265358979323846f;
                #pragma unroll
                for (int n = 1; n <= 6; n++) o[n - 1] = s * __sinf(((float)n * PIf) * x);
            }
        } else {
            int lim = E * 6 - base * 6;
            for (int idx = tid - 256; idx < 768; idx += 256)
                rbf_s[idx] = (idx < lim) ? rbf[base * 6 + idx] : 0.0f;
        }
        __syncthreads();

        // ---- Phase A: H fragments; each warp does 8 k-iters of one row-group ----
        {
            float rbA[6], rbB[6];
            #pragma unroll
            for (int j = 0; j < 6; j++) {
                rbA[j] = rbf_s[rA0 * 6 + j];
                rbB[j] = rbf_s[(rA0 + 8) * 6 + j];
            }
            #pragma unroll 2
            for (int kk = 0; kk < 8; kk++) {
                int k = kA + kk;
                int ca = 8 * k + q;
                const float* wA = Wr_s + ca * 6;
                float pa0 = brbf_s[ca],     pa1 = pa0;
                float pb0 = brbf_s[ca + 4], pb1 = pb0;
                #pragma unroll
                for (int j = 0; j < 6; j++) {
                    float wa = wA[j], wb = wA[24 + j];
                    pa0 += rbA[j] * wa;  pa1 += rbB[j] * wa;
                    pb0 += rbA[j] * wb;  pb1 += rbB[j] * wb;
                }
                uint2 v;
                v.x = pack_bf16(silu_f(pa1), silu_f(pa0));   // hi=row+8, lo=row
                v.y = pack_bf16(silu_f(pb1), silu_f(pb0));
                HFb[(rgA * 16 + k) * 32 + lane] = v;
            }
        }
        __syncthreads();

        // ---- Phase B: 16x64 warp tile, B via LDS.128, A via LDS.64 ----
        float c[8][4];
        #pragma unroll
        for (int nt = 0; nt < 8; nt++)
            { c[nt][0]=0.f; c[nt][1]=0.f; c[nt][2]=0.f; c[nt][3]=0.f; }

        #pragma unroll 4
        for (int k = 0; k < 16; k++) {
            int bb = (k * 8 + h * 4) * 32 + lane;
            uint4 b0 = BF4[bb], b1 = BF4[bb + 32], b2 = BF4[bb + 64], b3 = BF4[bb + 96];
            uint2 A0 = HFb[(m * 16 + k) * 32 + lane];
            unsigned a0 = A0.x << 16, a1 = A0.x & 0xFFFF0000u;
            unsigned a2 = A0.y << 16, a3 = A0.y & 0xFFFF0000u;
            mma_tf32(c[0], a0,a1,a2,a3, b0.x, b0.y);
            mma_tf32(c[1], a0,a1,a2,a3, b0.z, b0.w);
            mma_tf32(c[2], a0,a1,a2,a3, b1.x, b1.y);
            mma_tf32(c[3], a0,a1,a2,a3, b1.z, b1.w);
            mma_tf32(c[4], a0,a1,a2,a3, b2.x, b2.y);
            mma_tf32(c[5], a0,a1,a2,a3, b2.z, b2.w);
            mma_tf32(c[6], a0,a1,a2,a3, b3.x, b3.y);
            mma_tf32(c[7], a0,a1,a2,a3, b3.z, b3.w);
        }

        // ---- epilogue: + PT1[Z[src]] + PT2[Z[dst]], silu, store ----
        {
            int e0 = base + rB0, e1 = e0 + 8;
            const float* p1a = PTs + zs_s[rB0] * 258;
            const float* p2a = PTs + zd_s[rB0] * 258 + 128;
            const float* p1b = PTs + zs_s[rB0 + 8] * 258;
            const float* p2b = PTs + zd_s[rB0 + 8] * 258 + 128;
            float* o0 = out + (size_t)e0 * 128;
            float* o1 = out + (size_t)e1 * 128;
            bool st0 = (e0 < E), st1 = (e1 < E);
            #pragma unroll
            for (int nt = 0; nt < 8; nt++) {
                int col = h * 64 + nt * 8 + q * 2;
                float2 A1v = *(const float2*)(p1a + col);
                float2 A2v = *(const float2*)(p2a + col);
                float2 B1v = *(const float2*)(p1b + col);
                float2 B2v = *(const float2*)(p2b + col);
                float2 v0, v1;
                v0.x = silu_f(c[nt][0] + A1v.x + A2v.x);
                v0.y = silu_f(c[nt][1] + A1v.y + A2v.y);
                v1.x = silu_f(c[nt][2] + B1v.x + B2v.x);
                v1.y = silu_f(c[nt][3] + B1v.y + B2v.y);
                if (st0) *(float2*)(o0 + col) = v0;
                if (st1) *(float2*)(o1 + col) = v1;
            }
        }
    }
}

extern "C" void kernel_launch(void* const* d_in, const int* in_sizes, int n_in,
                              void* d_out, int out_size) {
    const int*   Z    = (const int*)d_in[0];
    const int*   src  = (const int*)d_in[1];
    const int*   dst  = (const int*)d_in[2];
    const float* rbf  = (const float*)d_in[3];
    const float* d    = (const float*)d_in[4];
    const float* emb  = (const float*)d_in[5];
    const float* Wr   = (const float*)d_in[6];
    const float* brbf = (const float*)d_in[7];
    const float* Wd   = (const float*)d_in[8];
    const float* bd   = (const float*)d_in[9];
    int E = in_sizes[1];
    int nTiles = (E + 127) / 128;

    precompute_kernel<<<N_TYPES + 64, 256>>>(emb, Wd, bd);

    cudaFuncSetAttribute(main_kernel, cudaFuncAttributeMaxDynamicSharedMemorySize, SMEM_BYTES);
    int dev = 0, nsm = 148;
    cudaGetDevice(&dev);
    cudaDeviceGetAttribute(&nsm, cudaDevAttrMultiProcessorCount, dev);

    main_kernel<<<nsm, 512, SMEM_BYTES>>>(Z, src, dst, rbf, d, Wr, brbf,
                                          (float*)d_out, E, nTiles);
}

// round 5
// speedup vs baseline: 1.9451x; 1.2249x over previous
#include <cuda_runtime.h>
#include <cstdint>

#define N_TYPES 95

// Precomputed constants (device globals: no allocation allowed)
__device__ float    g_PT[N_TYPES * 256];            // PT1 (with b_dense) | PT2
__device__ unsigned g_W3F[16384];                   // W3 tf32, mma B-fragment order
__device__ float    g_PTS[N_TYPES * N_TYPES * 128]; // PT1[zs]+PT2[zd] pair table (4.6MB)

__device__ __forceinline__ float silu_f(float x) {
    return __fdividef(x, 1.0f + __expf(-x));
}
__device__ __forceinline__ unsigned to_tf32(float x) {
    unsigned u; asm("cvt.rna.tf32.f32 %0, %1;" : "=r"(u) : "f"(x)); return u;
}
__device__ __forceinline__ unsigned pack_bf16(float hi, float lo) {
    unsigned r; asm("cvt.rn.bf16x2.f32 %0, %1, %2;" : "=r"(r) : "f"(hi), "f"(lo)); return r;
}
__device__ __forceinline__ void mma_tf32(float c[4],
                                         unsigned a0, unsigned a1, unsigned a2, unsigned a3,
                                         unsigned b0, unsigned b1) {
    asm volatile(
        "mma.sync.aligned.m16n8k8.row.col.f32.tf32.tf32.f32 "
        "{%0,%1,%2,%3}, {%4,%5,%6,%7}, {%8,%9}, {%0,%1,%2,%3};"
        : "+f"(c[0]), "+f"(c[1]), "+f"(c[2]), "+f"(c[3])
        : "r"(a0), "r"(a1), "r"(a2), "r"(a3), "r"(b0), "r"(b1));
}

// ---------------------------------------------------------------------------
// Precompute 1: PT[95][256] + W3 fragments (same layout as before)
// ---------------------------------------------------------------------------
__global__ void precompute_kernel(const float* __restrict__ emb,
                                  const float* __restrict__ Wd,
                                  const float* __restrict__ bd) {
    int b = blockIdx.x, t = threadIdx.x;
    if (b < N_TYPES) {
        __shared__ float er[128];
        if (t < 128) er[t] = emb[b * 128 + t];
        __syncthreads();
        int i = t & 127, half = t >> 7;
        const float4* w4 = (const float4*)(Wd + (size_t)i * 384 + half * 128);
        float acc = (half == 0) ? bd[i] : 0.0f;   // fold b_dense into PT1
        #pragma unroll
        for (int k4 = 0; k4 < 32; k4++) {
            float4 w = w4[k4];
            acc += er[k4*4+0]*w.x + er[k4*4+1]*w.y + er[k4*4+2]*w.z + er[k4*4+3]*w.w;
        }
        g_PT[b * 256 + half * 128 + i] = acc;
    } else {
        int idx  = (b - N_TYPES) * 256 + t;   // 0..16383
        int s    = idx & 3;
        int lane = (idx >> 2) & 31;
        int kgrp = idx >> 7;
        int k    = kgrp >> 3, ntgp = kgrp & 7;
        int ntg  = ntgp * 2 + (s >> 1);
        int bsel = s & 1;
        int col  = ntg * 8 + (lane >> 2);
        int kk   = k * 8 + (lane & 3) + bsel * 4;
        g_W3F[idx] = to_tf32(Wd[(size_t)col * 384 + 256 + kk]);
    }
}

// Precompute 2: pair-sum table PTS[zs*95+zd][i] = PT1[zs][i] + PT2[zd][i]
__global__ void ptsum_kernel() {
    int b = blockIdx.x;              // 0 .. 95*95-1
    int zs = b / N_TYPES, zd = b - zs * N_TYPES;
    int i = threadIdx.x;             // 0..127
    g_PTS[(size_t)b * 128 + i] = g_PT[zs * 256 + i] + g_PT[zd * 256 + 128 + i];
}

// ---------------------------------------------------------------------------
// Main fused kernel: persistent CTAs (1/SM), 512 threads, 128-edge tiles,
// cross-tile software pipeline with ONE barrier per tile:
//   iter: sync; [prefetch z-chain(t), bessel(t)]; fused { A(t+1) -> HF[p^1]
//   interleaved with B(t) from HF[p] }; epilogue(t) via global PTS table.
// ---------------------------------------------------------------------------
#define BF_WORDS 16384
#define HF_WORDS 8192               // one H buffer (bf16x2 pairs)
#define SMEM_WORDS (BF_WORDS + 2*HF_WORDS + 768 + 128)
#define SMEM_BYTES (SMEM_WORDS * 4) // 134,272 B

__global__ void __launch_bounds__(512, 1) main_kernel(
    const int* __restrict__ Z, const int* __restrict__ src, const int* __restrict__ dst,
    const float* __restrict__ rbf, const float* __restrict__ dvec,
    const float* __restrict__ Wr, const float* __restrict__ brbf,
    float* __restrict__ out, int E, int nTiles)
{
    extern __shared__ unsigned sm[];
    unsigned* BFs   = sm;
    uint2*    HF0   = (uint2*)(sm + BF_WORDS);
    uint2*    HF1   = HF0 + (HF_WORDS / 2);
    float*    Wr_s  = (float*)(sm + BF_WORDS + 2 * HF_WORDS);
    float*    brbf_s= Wr_s + 768;

    int tid = threadIdx.x;
    for (int i = tid; i < BF_WORDS; i += 512) BFs[i] = g_W3F[i];
    for (int i = tid; i < 768; i += 512) Wr_s[i] = Wr[i];
    if (tid < 128) brbf_s[tid] = brbf[tid];

    int lane = tid & 31, w = tid >> 5;
    int g = lane >> 2, q = lane & 3;
    int rgA = w & 7, kA = (w >> 3) * 8;   // phase A: row-group, k-range
    int rA0 = rgA * 16 + g;
    int m = w >> 1, h = w & 1;            // phase B: 16-row tile m, 64-col half h
    int rB0 = m * 16 + g;
    size_t envBase = (size_t)E * 128;
    const uint4* BF4 = (const uint4*)BFs;
    const float PIf = 3.14159265358979323846f;

    __syncthreads();   // Wr_s/brbf_s/BFs ready

    int t = blockIdx.x;
    int p = 0;
    if (t >= nTiles) return;

    // ---- prologue: A(t0) into HF0 ----
    {
        int basen = t * 128;
        int eA0 = min(basen + rA0, E - 1), eA1 = min(basen + rA0 + 8, E - 1);
        float rbA[6], rbB[6];
        #pragma unroll
        for (int j = 0; j < 6; j++) {
            rbA[j] = __ldg(rbf + (size_t)eA0 * 6 + j);
            rbB[j] = __ldg(rbf + (size_t)eA1 * 6 + j);
        }
        #pragma unroll
        for (int kk = 0; kk < 8; kk++) {
            int k = kA + kk, ca = 8 * k + q;
            const float* wA = Wr_s + ca * 6;
            float pa0 = brbf_s[ca],     pa1 = pa0;
            float pb0 = brbf_s[ca + 4], pb1 = pb0;
            #pragma unroll
            for (int j = 0; j < 6; j++) {
                float wa = wA[j], wb = wA[24 + j];
                pa0 += rbA[j] * wa;  pa1 += rbB[j] * wa;
                pb0 += rbA[j] * wb;  pb1 += rbB[j] * wb;
            }
            uint2 v;
            v.x = pack_bf16(silu_f(pa1), silu_f(pa0));
            v.y = pack_bf16(silu_f(pb1), silu_f(pb0));
            HF0[(rgA * 16 + k) * 32 + lane] = v;
        }
    }

    // ---- pipelined main loop: one barrier per tile ----
    while (t < nTiles) {
        __syncthreads();                       // HF[p] complete; prior reads done
        int base = t * 128;
        int tn = t + gridDim.x;
        uint2* HFr = p ? HF1 : HF0;            // B reads
        uint2* HFw = p ? HF0 : HF1;            // A writes

        // epilogue z-chain prefetch (long-latency, consumed after MMAs)
        int e0 = base + rB0, e1 = e0 + 8;
        int e0c = min(e0, E - 1), e1c = min(e1, E - 1);
        int s0 = __ldg(src + e0c), d0 = __ldg(dst + e0c);
        int s1 = __ldg(src + e1c), d1 = __ldg(dst + e1c);

        // bessel / envelope branch for tile t (global-only)
        if (tid < 128) {
            int e = base + tid;
            if (e < E) {
                float x = dvec[e] * 0.2f;
                float inv = 1.0f / x;
                float x2 = x*x, x4 = x2*x2, x5 = x4*x, x6 = x5*x, x7 = x6*x;
                float env = inv - 28.0f*x5 + 48.0f*x6 - 21.0f*x7;   // p = 6
                float s = env * inv;
                float* o = out + envBase + (size_t)e * 6;
                #pragma unroll
                for (int n = 1; n <= 6; n++) o[n - 1] = s * __sinf(((float)n * PIf) * x);
            }
        }

        int z0 = __ldg(Z + s0) * N_TYPES + __ldg(Z + d0);
        int z1 = __ldg(Z + s1) * N_TYPES + __ldg(Z + d1);
        const float* P0 = g_PTS + (size_t)z0 * 128;
        const float* P1 = g_PTS + (size_t)z1 * 128;

        // A(tn) inputs from global
        bool doA = (tn < nTiles);
        int basen = doA ? tn * 128 : 0;
        int eA0 = min(basen + rA0, E - 1), eA1 = min(basen + rA0 + 8, E - 1);
        float rbA[6], rbB[6];
        if (doA) {
            #pragma unroll
            for (int j = 0; j < 6; j++) {
                rbA[j] = __ldg(rbf + (size_t)eA0 * 6 + j);
                rbB[j] = __ldg(rbf + (size_t)eA1 * 6 + j);
            }
        }

        float c[8][4];
        #pragma unroll
        for (int nt = 0; nt < 8; nt++)
            { c[nt][0]=0.f; c[nt][1]=0.f; c[nt][2]=0.f; c[nt][3]=0.f; }

        // fused loop: 1 A-iter + 2 B-iters per step (mix FMA/MUFU with MMA/LDS)
        #pragma unroll 2
        for (int kk = 0; kk < 8; kk++) {
            if (doA) {
                int k = kA + kk, ca = 8 * k + q;
                const float* wA = Wr_s + ca * 6;
                float pa0 = brbf_s[ca],     pa1 = pa0;
                float pb0 = brbf_s[ca + 4], pb1 = pb0;
                #pragma unroll
                for (int j = 0; j < 6; j++) {
                    float wa = wA[j], wb = wA[24 + j];
                    pa0 += rbA[j] * wa;  pa1 += rbB[j] * wa;
                    pb0 += rbA[j] * wb;  pb1 += rbB[j] * wb;
                }
                uint2 v;
                v.x = pack_bf16(silu_f(pa1), silu_f(pa0));
                v.y = pack_bf16(silu_f(pb1), silu_f(pb0));
                HFw[(rgA * 16 + k) * 32 + lane] = v;
            }
            #pragma unroll
            for (int ks = 0; ks < 2; ks++) {
                int k = 2 * kk + ks;
                int bb = (k * 8 + h * 4) * 32 + lane;
                uint4 b0 = BF4[bb], b1 = BF4[bb + 32], b2 = BF4[bb + 64], b3 = BF4[bb + 96];
                uint2 A0 = HFr[(m * 16 + k) * 32 + lane];
                unsigned a0 = A0.x << 16, a1 = A0.x & 0xFFFF0000u;
                unsigned a2 = A0.y << 16, a3 = A0.y & 0xFFFF0000u;
                mma_tf32(c[0], a0,a1,a2,a3, b0.x, b0.y);
                mma_tf32(c[1], a0,a1,a2,a3, b0.z, b0.w);
                mma_tf32(c[2], a0,a1,a2,a3, b1.x, b1.y);
                mma_tf32(c[3], a0,a1,a2,a3, b1.z, b1.w);
                mma_tf32(c[4], a0,a1,a2,a3, b2.x, b2.y);
                mma_tf32(c[5], a0,a1,a2,a3, b2.z, b2.w);
                mma_tf32(c[6], a0,a1,a2,a3, b3.x, b3.y);
                mma_tf32(c[7], a0,a1,a2,a3, b3.z, b3.w);
            }
        }

        // ---- epilogue: + PTS[zs,zd] (pair table, L2), silu, store ----
        {
            float* o0 = out + (size_t)e0 * 128;
            float* o1 = out + (size_t)e1 * 128;
            bool st0 = (e0 < E), st1 = (e1 < E);
            #pragma unroll
            for (int nt = 0; nt < 8; nt++) {
                int col = h * 64 + nt * 8 + q * 2;
                float2 A1v = __ldg((const float2*)(P0 + col));
                float2 B1v = __ldg((const float2*)(P1 + col));
                float2 v0, v1;
                v0.x = silu_f(c[nt][0] + A1v.x);
                v0.y = silu_f(c[nt][1] + A1v.y);
                v1.x = silu_f(c[nt][2] + B1v.x);
                v1.y = silu_f(c[nt][3] + B1v.y);
                if (st0) *(float2*)(o0 + col) = v0;
                if (st1) *(float2*)(o1 + col) = v1;
            }
        }

        t = tn; p ^= 1;
    }
}

extern "C" void kernel_launch(void* const* d_in, const int* in_sizes, int n_in,
                              void* d_out, int out_size) {
    const int*   Z    = (const int*)d_in[0];
    const int*   src  = (const int*)d_in[1];
    const int*   dst  = (const int*)d_in[2];
    const float* rbf  = (const float*)d_in[3];
    const float* d    = (const float*)d_in[4];
    const float* emb  = (const float*)d_in[5];
    const float* Wr   = (const float*)d_in[6];
    const float* brbf = (const float*)d_in[7];
    const float* Wd   = (const float*)d_in[8];
    const float* bd   = (const float*)d_in[9];
    int E = in_sizes[1];
    int nTiles = (E + 127) / 128;

    precompute_kernel<<<N_TYPES + 64, 256>>>(emb, Wd, bd);
    ptsum_kernel<<<N_TYPES * N_TYPES, 128>>>();

    cudaFuncSetAttribute(main_kernel, cudaFuncAttributeMaxDynamicSharedMemorySize, SMEM_BYTES);
    int dev = 0, nsm = 148;
    cudaGetDevice(&dev);
    cudaDeviceGetAttribute(&nsm, cudaDevAttrMultiProcessorCount, dev);

    main_kernel<<<nsm, 512, SMEM_BYTES>>>(Z, src, dst, rbf, d, Wr, brbf,
                                          (float*)d_out, E, nTiles);
}

// round 6
// speedup vs baseline: 2.0195x; 1.0383x over previous
#include <cuda_runtime.h>
#include <cstdint>

#define N_TYPES 95

// Precomputed constants (device globals: no allocation allowed)
__device__ float    g_PT[N_TYPES * 256];            // PT1 (with b_dense) | PT2
__device__ unsigned g_W3F[16384];                   // W3 tf32, mma B-fragment order
__device__ float    g_PTS[N_TYPES * N_TYPES * 128]; // PT1[zs]+PT2[zd] pair table (4.6MB)

__device__ __forceinline__ float silu_f(float x) {
    return __fdividef(x, 1.0f + __expf(-x));
}
__device__ __forceinline__ unsigned to_tf32(float x) {
    unsigned u; asm("cvt.rna.tf32.f32 %0, %1;" : "=r"(u) : "f"(x)); return u;
}
__device__ __forceinline__ unsigned pack_bf16(float hi, float lo) {
    unsigned r; asm("cvt.rn.bf16x2.f32 %0, %1, %2;" : "=r"(r) : "f"(hi), "f"(lo)); return r;
}
__device__ __forceinline__ void mma_tf32(float c[4],
                                         unsigned a0, unsigned a1, unsigned a2, unsigned a3,
                                         unsigned b0, unsigned b1) {
    asm volatile(
        "mma.sync.aligned.m16n8k8.row.col.f32.tf32.tf32.f32 "
        "{%0,%1,%2,%3}, {%4,%5,%6,%7}, {%8,%9}, {%0,%1,%2,%3};"
        : "+f"(c[0]), "+f"(c[1]), "+f"(c[2]), "+f"(c[3])
        : "r"(a0), "r"(a1), "r"(a2), "r"(a3), "r"(b0), "r"(b1));
}

// ---------------------------------------------------------------------------
// Precompute 1: PT[95][256] + W3 fragments
// Fragment layout: uint4 index (k*8 + ntgp)*32 + lane holds, for lane (g,q):
//   .x = W3[col=2ntgp*8+g][k*8+q]      .y = W3[same col][k*8+q+4]
//   .z = W3[col=(2ntgp+1)*8+g][k*8+q]  .w = W3[same col][k*8+q+4]
// ---------------------------------------------------------------------------
__global__ void precompute_kernel(const float* __restrict__ emb,
                                  const float* __restrict__ Wd,
                                  const float* __restrict__ bd) {
    int b = blockIdx.x, t = threadIdx.x;
    if (b < N_TYPES) {
        __shared__ float er[128];
        if (t < 128) er[t] = emb[b * 128 + t];
        __syncthreads();
        int i = t & 127, half = t >> 7;
        const float4* w4 = (const float4*)(Wd + (size_t)i * 384 + half * 128);
        float acc = (half == 0) ? bd[i] : 0.0f;   // fold b_dense into PT1
        #pragma unroll
        for (int k4 = 0; k4 < 32; k4++) {
            float4 w = w4[k4];
            acc += er[k4*4+0]*w.x + er[k4*4+1]*w.y + er[k4*4+2]*w.z + er[k4*4+3]*w.w;
        }
        g_PT[b * 256 + half * 128 + i] = acc;
    } else {
        int idx  = (b - N_TYPES) * 256 + t;   // 0..16383
        int s    = idx & 3;
        int lane = (idx >> 2) & 31;
        int kgrp = idx >> 7;
        int k    = kgrp >> 3, ntgp = kgrp & 7;
        int ntg  = ntgp * 2 + (s >> 1);
        int bsel = s & 1;
        int col  = ntg * 8 + (lane >> 2);
        int kk   = k * 8 + (lane & 3) + bsel * 4;
        g_W3F[idx] = to_tf32(Wd[(size_t)col * 384 + 256 + kk]);
    }
}

// Precompute 2: pair-sum table PTS[zs*95+zd][i] = PT1[zs][i] + PT2[zd][i]
__global__ void ptsum_kernel() {
    int b = blockIdx.x;              // 0 .. 95*95-1
    int zs = b / N_TYPES, zd = b - zs * N_TYPES;
    int i = threadIdx.x;             // 0..127
    g_PTS[(size_t)b * 128 + i] = g_PT[zs * 256 + i] + g_PT[zd * 256 + 128 + i];
}

// ---------------------------------------------------------------------------
// Main fused kernel: persistent CTAs (1/SM), 512 threads, 128-edge tiles,
// cross-tile software pipeline, ONE barrier per tile.
// Phase B partition: warp w -> M-group mq=w>>2 (32 rows), col quarter h=w&3
// (32 cols). Each B fragment (2x LDS.128 per k) reused across 2 M-subtiles.
// ---------------------------------------------------------------------------
#define BF_WORDS 16384
#define HF_WORDS 8192               // one H buffer (bf16x2 pairs)
#define SMEM_WORDS (BF_WORDS + 2*HF_WORDS + 768 + 128)
#define SMEM_BYTES (SMEM_WORDS * 4) // 134,272 B

__global__ void __launch_bounds__(512, 1) main_kernel(
    const int* __restrict__ Z, const int* __restrict__ src, const int* __restrict__ dst,
    const float* __restrict__ rbf, const float* __restrict__ dvec,
    const float* __restrict__ Wr, const float* __restrict__ brbf,
    float* __restrict__ out, int E, int nTiles)
{
    extern __shared__ unsigned sm[];
    unsigned* BFs   = sm;
    uint2*    HF0   = (uint2*)(sm + BF_WORDS);
    uint2*    HF1   = HF0 + (HF_WORDS / 2);
    float*    Wr_s  = (float*)(sm + BF_WORDS + 2 * HF_WORDS);
    float*    brbf_s= Wr_s + 768;

    int tid = threadIdx.x;
    for (int i = tid; i < BF_WORDS; i += 512) BFs[i] = g_W3F[i];
    for (int i = tid; i < 768; i += 512) Wr_s[i] = Wr[i];
    if (tid < 128) brbf_s[tid] = brbf[tid];

    int lane = tid & 31, w = tid >> 5;
    int g = lane >> 2, q = lane & 3;
    int rgA = w & 7, kA = (w >> 3) * 8;   // phase A: row-group, k-range
    int rA0 = rgA * 16 + g;
    int mq = w >> 2, h = w & 3;           // phase B: 32-row group, 32-col quarter
    size_t envBase = (size_t)E * 128;
    const uint4* BF4 = (const uint4*)BFs;
    const float PIf = 3.14159265358979323846f;

    __syncthreads();   // Wr_s/brbf_s/BFs ready

    int t = blockIdx.x;
    int p = 0;
    if (t >= nTiles) return;

    // ---- prologue: A(t0) into HF0 ----
    {
        int basen = t * 128;
        int eA0 = min(basen + rA0, E - 1), eA1 = min(basen + rA0 + 8, E - 1);
        float rbA[6], rbB[6];
        #pragma unroll
        for (int j = 0; j < 6; j++) {
            rbA[j] = __ldg(rbf + (size_t)eA0 * 6 + j);
            rbB[j] = __ldg(rbf + (size_t)eA1 * 6 + j);
        }
        #pragma unroll
        for (int kk = 0; kk < 8; kk++) {
            int k = kA + kk, ca = 8 * k + q;
            const float* wA = Wr_s + ca * 6;
            float pa0 = brbf_s[ca],     pa1 = pa0;
            float pb0 = brbf_s[ca + 4], pb1 = pb0;
            #pragma unroll
            for (int j = 0; j < 6; j++) {
                float wa = wA[j], wb = wA[24 + j];
                pa0 += rbA[j] * wa;  pa1 += rbB[j] * wa;
                pb0 += rbA[j] * wb;  pb1 += rbB[j] * wb;
            }
            uint2 v;
            v.x = pack_bf16(silu_f(pa1), silu_f(pa0));
            v.y = pack_bf16(silu_f(pb1), silu_f(pb0));
            HF0[(rgA * 16 + k) * 32 + lane] = v;
        }
    }

    // ---- pipelined main loop: one barrier per tile ----
    while (t < nTiles) {
        __syncthreads();                       // HF[p] complete; prior reads done
        int base = t * 128;
        int tn = t + gridDim.x;
        uint2* HFr = p ? HF1 : HF0;            // B reads
        uint2* HFw = p ? HF0 : HF1;            // A writes

        // epilogue z-chain prefetch (long-latency, consumed after MMAs)
        int r0 = (2 * mq) * 16 + g;            // mt=0 base row
        int r1 = r0 + 16;                      // mt=1 base row
        int e00 = base + r0, e01 = e00 + 8;
        int e10 = base + r1, e11 = e10 + 8;
        int c00 = min(e00, E - 1), c01 = min(e01, E - 1);
        int c10 = min(e10, E - 1), c11 = min(e11, E - 1);
        int s00 = __ldg(src + c00), d00 = __ldg(dst + c00);
        int s01 = __ldg(src + c01), d01 = __ldg(dst + c01);
        int s10 = __ldg(src + c10), d10 = __ldg(dst + c10);
        int s11 = __ldg(src + c11), d11 = __ldg(dst + c11);

        // bessel / envelope branch for tile t (global-only)
        if (tid < 128) {
            int e = base + tid;
            if (e < E) {
                float x = dvec[e] * 0.2f;
                float inv = 1.0f / x;
                float x2 = x*x, x4 = x2*x2, x5 = x4*x, x6 = x5*x, x7 = x6*x;
                float env = inv - 28.0f*x5 + 48.0f*x6 - 21.0f*x7;   // p = 6
                float s = env * inv;
                float* o = out + envBase + (size_t)e * 6;
                #pragma unroll
                for (int n = 1; n <= 6; n++) o[n - 1] = s * __sinf(((float)n * PIf) * x);
            }
        }

        const float* P00 = g_PTS + ((size_t)__ldg(Z + s00) * N_TYPES + __ldg(Z + d00)) * 128;
        const float* P01 = g_PTS + ((size_t)__ldg(Z + s01) * N_TYPES + __ldg(Z + d01)) * 128;
        const float* P10 = g_PTS + ((size_t)__ldg(Z + s10) * N_TYPES + __ldg(Z + d10)) * 128;
        const float* P11 = g_PTS + ((size_t)__ldg(Z + s11) * N_TYPES + __ldg(Z + d11)) * 128;

        // A(tn) inputs from global
        bool doA = (tn < nTiles);
        int basen = doA ? tn * 128 : 0;
        int eA0 = min(basen + rA0, E - 1), eA1 = min(basen + rA0 + 8, E - 1);
        float rbA[6], rbB[6];
        if (doA) {
            #pragma unroll
            for (int j = 0; j < 6; j++) {
                rbA[j] = __ldg(rbf + (size_t)eA0 * 6 + j);
                rbB[j] = __ldg(rbf + (size_t)eA1 * 6 + j);
            }
        }

        float c[2][4][4];
        #pragma unroll
        for (int mt = 0; mt < 2; mt++)
            #pragma unroll
            for (int nt = 0; nt < 4; nt++)
                { c[mt][nt][0]=0.f; c[mt][nt][1]=0.f; c[mt][nt][2]=0.f; c[mt][nt][3]=0.f; }

        // fused loop: 1 A-iter + 2 B-iters per step (mix FMA/MUFU with MMA/LDS)
        #pragma unroll 2
        for (int kk = 0; kk < 8; kk++) {
            if (doA) {
                int k = kA + kk, ca = 8 * k + q;
                const float* wA = Wr_s + ca * 6;
                float pa0 = brbf_s[ca],     pa1 = pa0;
                float pb0 = brbf_s[ca + 4], pb1 = pb0;
                #pragma unroll
                for (int j = 0; j < 6; j++) {
                    float wa = wA[j], wb = wA[24 + j];
                    pa0 += rbA[j] * wa;  pa1 += rbB[j] * wa;
                    pb0 += rbA[j] * wb;  pb1 += rbB[j] * wb;
                }
                uint2 v;
                v.x = pack_bf16(silu_f(pa1), silu_f(pa0));
                v.y = pack_bf16(silu_f(pb1), silu_f(pb0));
                HFw[(rgA * 16 + k) * 32 + lane] = v;
            }
            #pragma unroll
            for (int ks = 0; ks < 2; ks++) {
                int k = 2 * kk + ks;
                int bb = (k * 8 + h * 2) * 32 + lane;
                uint4 b0 = BF4[bb], b1 = BF4[bb + 32];
                uint2 Am0 = HFr[((2 * mq)     * 16 + k) * 32 + lane];
                uint2 Am1 = HFr[((2 * mq + 1) * 16 + k) * 32 + lane];
                unsigned a00 = Am0.x << 16, a01 = Am0.x & 0xFFFF0000u;
                unsigned a02 = Am0.y << 16, a03 = Am0.y & 0xFFFF0000u;
                unsigned a10 = Am1.x << 16, a11 = Am1.x & 0xFFFF0000u;
                unsigned a12 = Am1.y << 16, a13 = Am1.y & 0xFFFF0000u;
                mma_tf32(c[0][0], a00,a01,a02,a03, b0.x, b0.y);
                mma_tf32(c[0][1], a00,a01,a02,a03, b0.z, b0.w);
                mma_tf32(c[0][2], a00,a01,a02,a03, b1.x, b1.y);
                mma_tf32(c[0][3], a00,a01,a02,a03, b1.z, b1.w);
                mma_tf32(c[1][0], a10,a11,a12,a13, b0.x, b0.y);
                mma_tf32(c[1][1], a10,a11,a12,a13, b0.z, b0.w);
                mma_tf32(c[1][2], a10,a11,a12,a13, b1.x, b1.y);
                mma_tf32(c[1][3], a10,a11,a12,a13, b1.z, b1.w);
            }
        }

        // ---- epilogue: + PTS[zs,zd] (pair table, L2), silu, store ----
        #pragma unroll
        for (int mt = 0; mt < 2; mt++) {
            int e0 = mt ? e10 : e00;
            int e1 = mt ? e11 : e01;
            const float* Pa = mt ? P10 : P00;
            const float* Pb = mt ? P11 : P01;
            float* o0 = out + (size_t)e0 * 128;
            float* o1 = out + (size_t)e1 * 128;
            bool st0 = (e0 < E), st1 = (e1 < E);
            #pragma unroll
            for (int nt = 0; nt < 4; nt++) {
                int col = h * 32 + nt * 8 + q * 2;
                float2 A1v = __ldg((const float2*)(Pa + col));
                float2 B1v = __ldg((const float2*)(Pb + col));
                float2 v0, v1;
                v0.x = silu_f(c[mt][nt][0] + A1v.x);
                v0.y = silu_f(c[mt][nt][1] + A1v.y);
                v1.x = silu_f(c[mt][nt][2] + B1v.x);
                v1.y = silu_f(c[mt][nt][3] + B1v.y);
                if (st0) *(float2*)(o0 + col) = v0;
                if (st1) *(float2*)(o1 + col) = v1;
            }
        }

        t = tn; p ^= 1;
    }
}

extern "C" void kernel_launch(void* const* d_in, const int* in_sizes, int n_in,
                              void* d_out, int out_size) {
    const int*   Z    = (const int*)d_in[0];
    const int*   src  = (const int*)d_in[1];
    const int*   dst  = (const int*)d_in[2];
    const float* rbf  = (const float*)d_in[3];
    const float* d    = (const float*)d_in[4];
    const float* emb  = (const float*)d_in[5];
    const float* Wr   = (const float*)d_in[6];
    const float* brbf = (const float*)d_in[7];
    const float* Wd   = (const float*)d_in[8];
    const float* bd   = (const float*)d_in[9];
    int E = in_sizes[1];
    int nTiles = (E + 127) / 128;

    precompute_kernel<<<N_TYPES + 64, 256>>>(emb, Wd, bd);
    ptsum_kernel<<<N_TYPES * N_TYPES, 128>>>();

    cudaFuncSetAttribute(main_kernel, cudaFuncAttributeMaxDynamicSharedMemorySize, SMEM_BYTES);
    int dev = 0, nsm = 148;
    cudaGetDevice(&dev);
    cudaDeviceGetAttribute(&nsm, cudaDevAttrMultiProcessorCount, dev);

    main_kernel<<<nsm, 512, SMEM_BYTES>>>(Z, src, dst, rbf, d, Wr, brbf,
                                          (float*)d_out, E, nTiles);
}

// round 8
// speedup vs baseline: 2.0966x; 1.0382x over previous
#include <cuda_runtime.h>
#include <cstdint>

#define N_TYPES 95

// Precomputed constants (device globals: no allocation allowed)
__device__ float    g_PT[N_TYPES * 256];            // PT1 (with b_dense) | PT2
__device__ unsigned g_W3F[16384];                   // W3 tf32, mma B-fragment order
__device__ float    g_PTS[N_TYPES * N_TYPES * 128]; // PT1[zs]+PT2[zd] pair table (4.6MB)

// silu via tanh: x*sigmoid(x) = h + h*tanh(h), h = x/2.  1 MUFU instead of 2.
__device__ __forceinline__ float silu_f(float x) {
    float h = 0.5f * x, t;
    asm("tanh.approx.f32 %0, %1;" : "=f"(t) : "f"(h));
    return fmaf(h, t, h);
}
__device__ __forceinline__ unsigned to_tf32(float x) {
    unsigned u; asm("cvt.rna.tf32.f32 %0, %1;" : "=r"(u) : "f"(x)); return u;
}
__device__ __forceinline__ unsigned pack_bf16(float hi, float lo) {
    unsigned r; asm("cvt.rn.bf16x2.f32 %0, %1, %2;" : "=r"(r) : "f"(hi), "f"(lo)); return r;
}
__device__ __forceinline__ void mma_tf32(float c[4],
                                         unsigned a0, unsigned a1, unsigned a2, unsigned a3,
                                         unsigned b0, unsigned b1) {
    asm volatile(
        "mma.sync.aligned.m16n8k8.row.col.f32.tf32.tf32.f32 "
        "{%0,%1,%2,%3}, {%4,%5,%6,%7}, {%8,%9}, {%0,%1,%2,%3};"
        : "+f"(c[0]), "+f"(c[1]), "+f"(c[2]), "+f"(c[3])
        : "r"(a0), "r"(a1), "r"(a2), "r"(a3), "r"(b0), "r"(b1));
}

// ---------------------------------------------------------------------------
// Precompute 1: PT[95][256] + W3 fragments
// Fragment layout: uint4 index (k*8 + ntgp)*32 + lane holds, for lane (g,q):
//   .x = W3[col=2ntgp*8+g][k*8+q]      .y = W3[same col][k*8+q+4]
//   .z = W3[col=(2ntgp+1)*8+g][k*8+q]  .w = W3[same col][k*8+q+4]
// ---------------------------------------------------------------------------
__global__ void precompute_kernel(const float* __restrict__ emb,
                                  const float* __restrict__ Wd,
                                  const float* __restrict__ bd) {
    int b = blockIdx.x, t = threadIdx.x;
    if (b < N_TYPES) {
        __shared__ float er[128];
        if (t < 128) er[t] = emb[b * 128 + t];
        __syncthreads();
        int i = t & 127, half = t >> 7;
        const float4* w4 = (const float4*)(Wd + (size_t)i * 384 + half * 128);
        float acc = (half == 0) ? bd[i] : 0.0f;   // fold b_dense into PT1
        #pragma unroll
        for (int k4 = 0; k4 < 32; k4++) {
            float4 w = w4[k4];
            acc += er[k4*4+0]*w.x + er[k4*4+1]*w.y + er[k4*4+2]*w.z + er[k4*4+3]*w.w;
        }
        g_PT[b * 256 + half * 128 + i] = acc;
    } else {
        int idx  = (b - N_TYPES) * 256 + t;   // 0..16383
        int s    = idx & 3;
        int lane = (idx >> 2) & 31;
        int kgrp = idx >> 7;
        int k    = kgrp >> 3, ntgp = kgrp & 7;
        int ntg  = ntgp * 2 + (s >> 1);
        int bsel = s & 1;
        int col  = ntg * 8 + (lane >> 2);
        int kk   = k * 8 + (lane & 3) + bsel * 4;
        g_W3F[idx] = to_tf32(Wd[(size_t)col * 384 + 256 + kk]);
    }
}

// Precompute 2: pair-sum table PTS[zs*95+zd][i] = PT1[zs][i] + PT2[zd][i]
__global__ void ptsum_kernel() {
    int b = blockIdx.x;              // 0 .. 95*95-1
    int zs = b / N_TYPES, zd = b - zs * N_TYPES;
    int i = threadIdx.x;             // 0..127
    g_PTS[(size_t)b * 128 + i] = g_PT[zs * 256 + i] + g_PT[zd * 256 + 128 + i];
}

// ---------------------------------------------------------------------------
// Main fused kernel: persistent CTAs (1/SM), 512 threads, 128-edge tiles,
// cross-tile software pipeline, ONE barrier per tile.
// Phase B partition: warp w -> M-group mq=w>>2 (32 rows), col quarter h=w&3
// (32 cols). Each B fragment (2x LDS.128 per k) reused across 2 M-subtiles.
// ---------------------------------------------------------------------------
#define BF_WORDS 16384
#define HF_WORDS 8192               // one H buffer (bf16x2 pairs)
#define SMEM_WORDS (BF_WORDS + 2*HF_WORDS + 768 + 128)
#define SMEM_BYTES (SMEM_WORDS * 4) // 134,272 B

__global__ void __launch_bounds__(512, 1) main_kernel(
    const int* __restrict__ Z, const int* __restrict__ src, const int* __restrict__ dst,
    const float* __restrict__ rbf, const float* __restrict__ dvec,
    const float* __restrict__ Wr, const float* __restrict__ brbf,
    float* __restrict__ out, int E, int nTiles)
{
    extern __shared__ unsigned sm[];
    unsigned* BFs   = sm;
    uint2*    HF0   = (uint2*)(sm + BF_WORDS);
    uint2*    HF1   = HF0 + (HF_WORDS / 2);
    float*    Wr_s  = (float*)(sm + BF_WORDS + 2 * HF_WORDS);
    float*    brbf_s= Wr_s + 768;

    int tid = threadIdx.x;
    for (int i = tid; i < BF_WORDS; i += 512) BFs[i] = g_W3F[i];
    for (int i = tid; i < 768; i += 512) Wr_s[i] = Wr[i];
    if (tid < 128) brbf_s[tid] = brbf[tid];

    int lane = tid & 31, w = tid >> 5;
    int g = lane >> 2, q = lane & 3;
    int rgA = w & 7, kA = (w >> 3) * 8;   // phase A: row-group, k-range
    int rA0 = rgA * 16 + g;
    int mq = w >> 2, h = w & 3;           // phase B: 32-row group, 32-col quarter
    size_t envBase = (size_t)E * 128;
    const uint4* BF4 = (const uint4*)BFs;
    const float PIf = 3.14159265358979323846f;

    __syncthreads();   // Wr_s/brbf_s/BFs ready

    int t = blockIdx.x;
    int p = 0;
    if (t >= nTiles) return;

    // ---- prologue: A(t0) into HF0 ----
    {
        int basen = t * 128;
        int eA0 = min(basen + rA0, E - 1), eA1 = min(basen + rA0 + 8, E - 1);
        float rbA[6], rbB[6];
        #pragma unroll
        for (int j = 0; j < 6; j++) {
            rbA[j] = __ldg(rbf + (size_t)eA0 * 6 + j);
            rbB[j] = __ldg(rbf + (size_t)eA1 * 6 + j);
        }
        #pragma unroll
        for (int kk = 0; kk < 8; kk++) {
            int k = kA + kk, ca = 8 * k + q;
            const float* wA = Wr_s + ca * 6;
            float pa0 = brbf_s[ca],     pa1 = pa0;
            float pb0 = brbf_s[ca + 4], pb1 = pb0;
            #pragma unroll
            for (int j = 0; j < 6; j++) {
                float wa = wA[j], wb = wA[24 + j];
                pa0 += rbA[j] * wa;  pa1 += rbB[j] * wa;
                pb0 += rbA[j] * wb;  pb1 += rbB[j] * wb;
            }
            uint2 v;
            v.x = pack_bf16(silu_f(pa1), silu_f(pa0));
            v.y = pack_bf16(silu_f(pb1), silu_f(pb0));
            HF0[(rgA * 16 + k) * 32 + lane] = v;
        }
    }

    // ---- pipelined main loop: one barrier per tile ----
    while (t < nTiles) {
        __syncthreads();                       // HF[p] complete; prior reads done
        int base = t * 128;
        int tn = t + gridDim.x;
        uint2* HFr = p ? HF1 : HF0;            // B reads
        uint2* HFw = p ? HF0 : HF1;            // A writes

        // epilogue z-chain prefetch (long-latency, consumed after MMAs)
        int r0 = (2 * mq) * 16 + g;            // mt=0 base row
        int r1 = r0 + 16;                      // mt=1 base row
        int e00 = base + r0, e01 = e00 + 8;
        int e10 = base + r1, e11 = e10 + 8;
        int c00 = min(e00, E - 1), c01 = min(e01, E - 1);
        int c10 = min(e10, E - 1), c11 = min(e11, E - 1);
        int s00 = __ldg(src + c00), d00 = __ldg(dst + c00);
        int s01 = __ldg(src + c01), d01 = __ldg(dst + c01);
        int s10 = __ldg(src + c10), d10 = __ldg(dst + c10);
        int s11 = __ldg(src + c11), d11 = __ldg(dst + c11);

        // bessel / envelope branch for tile t: 256 threads, 3 sins each
        if (tid < 256) {
            int e = base + (tid >> 1);
            if (e < E) {
                int half3 = (tid & 1) * 3;
                float x = dvec[e] * 0.2f;
                float inv = 1.0f / x;
                float x2 = x*x, x4 = x2*x2, x5 = x4*x, x6 = x5*x, x7 = x6*x;
                float env = inv - 28.0f*x5 + 48.0f*x6 - 21.0f*x7;   // p = 6
                float s = env * inv;
                float* oo = out + envBase + (size_t)e * 6 + half3;
                #pragma unroll
                for (int n = 1; n <= 3; n++)
                    oo[n - 1] = s * __sinf(((float)(n + half3) * PIf) * x);
            }
        }

        const float* P00 = g_PTS + ((size_t)__ldg(Z + s00) * N_TYPES + __ldg(Z + d00)) * 128;
        const float* P01 = g_PTS + ((size_t)__ldg(Z + s01) * N_TYPES + __ldg(Z + d01)) * 128;
        const float* P10 = g_PTS + ((size_t)__ldg(Z + s10) * N_TYPES + __ldg(Z + d10)) * 128;
        const float* P11 = g_PTS + ((size_t)__ldg(Z + s11) * N_TYPES + __ldg(Z + d11)) * 128;

        // prefetch mt=0 pair-table values (hidden behind the MMA k-loop)
        float2 pts0a[4], pts0b[4];
        #pragma unroll
        for (int nt = 0; nt < 4; nt++) {
            int col = h * 32 + nt * 8 + q * 2;
            pts0a[nt] = __ldg((const float2*)(P00 + col));
            pts0b[nt] = __ldg((const float2*)(P01 + col));
        }

        // A(tn) inputs from global
        bool doA = (tn < nTiles);
        int basen = doA ? tn * 128 : 0;
        int eA0 = min(basen + rA0, E - 1), eA1 = min(basen + rA0 + 8, E - 1);
        float rbA[6], rbB[6];
        if (doA) {
            #pragma unroll
            for (int j = 0; j < 6; j++) {
                rbA[j] = __ldg(rbf + (size_t)eA0 * 6 + j);
                rbB[j] = __ldg(rbf + (size_t)eA1 * 6 + j);
            }
        }

        float c[2][4][4];
        #pragma unroll
        for (int mt = 0; mt < 2; mt++)
            #pragma unroll
            for (int nt = 0; nt < 4; nt++)
                { c[mt][nt][0]=0.f; c[mt][nt][1]=0.f; c[mt][nt][2]=0.f; c[mt][nt][3]=0.f; }

        // fused loop: 1 A-iter + 2 B-iters per step (mix FMA/MUFU with MMA/LDS)
        #pragma unroll 2
        for (int kk = 0; kk < 8; kk++) {
            if (doA) {
                int k = kA + kk, ca = 8 * k + q;
                const float* wA = Wr_s + ca * 6;
                float pa0 = brbf_s[ca],     pa1 = pa0;
                float pb0 = brbf_s[ca + 4], pb1 = pb0;
                #pragma unroll
                for (int j = 0; j < 6; j++) {
                    float wa = wA[j], wb = wA[24 + j];
                    pa0 += rbA[j] * wa;  pa1 += rbB[j] * wa;
                    pb0 += rbA[j] * wb;  pb1 += rbB[j] * wb;
                }
                uint2 v;
                v.x = pack_bf16(silu_f(pa1), silu_f(pa0));
                v.y = pack_bf16(silu_f(pb1), silu_f(pb0));
                HFw[(rgA * 16 + k) * 32 + lane] = v;
            }
            #pragma unroll
            for (int ks = 0; ks < 2; ks++) {
                int k = 2 * kk + ks;
                int bb = (k * 8 + h * 2) * 32 + lane;
                uint4 b0 = BF4[bb], b1 = BF4[bb + 32];
                uint2 Am0 = HFr[((2 * mq)     * 16 + k) * 32 + lane];
                uint2 Am1 = HFr[((2 * mq + 1) * 16 + k) * 32 + lane];
                unsigned a00 = Am0.x << 16, a01 = Am0.x & 0xFFFF0000u;
                unsigned a02 = Am0.y << 16, a03 = Am0.y & 0xFFFF0000u;
                unsigned a10 = Am1.x << 16, a11 = Am1.x & 0xFFFF0000u;
                unsigned a12 = Am1.y << 16, a13 = Am1.y & 0xFFFF0000u;
                mma_tf32(c[0][0], a00,a01,a02,a03, b0.x, b0.y);
                mma_tf32(c[0][1], a00,a01,a02,a03, b0.z, b0.w);
                mma_tf32(c[0][2], a00,a01,a02,a03, b1.x, b1.y);
                mma_tf32(c[0][3], a00,a01,a02,a03, b1.z, b1.w);
                mma_tf32(c[1][0], a10,a11,a12,a13, b0.x, b0.y);
                mma_tf32(c[1][1], a10,a11,a12,a13, b0.z, b0.w);
                mma_tf32(c[1][2], a10,a11,a12,a13, b1.x, b1.y);
                mma_tf32(c[1][3], a10,a11,a12,a13, b1.z, b1.w);
            }
        }

        // mt=1 pair-table loads issued now (hidden behind mt=0 epilogue)
        float2 pts1a[4], pts1b[4];
        #pragma unroll
        for (int nt = 0; nt < 4; nt++) {
            int col = h * 32 + nt * 8 + q * 2;
            pts1a[nt] = __ldg((const float2*)(P10 + col));
            pts1b[nt] = __ldg((const float2*)(P11 + col));
        }

        // ---- epilogue mt=0 ----
        {
            float* o0 = out + (size_t)e00 * 128;
            float* o1 = out + (size_t)e01 * 128;
            bool st0 = (e00 < E), st1 = (e01 < E);
            #pragma unroll
            for (int nt = 0; nt < 4; nt++) {
                int col = h * 32 + nt * 8 + q * 2;
                float2 v0, v1;
                v0.x = silu_f(c[0][nt][0] + pts0a[nt].x);
                v0.y = silu_f(c[0][nt][1] + pts0a[nt].y);
                v1.x = silu_f(c[0][nt][2] + pts0b[nt].x);
                v1.y = silu_f(c[0][nt][3] + pts0b[nt].y);
                if (st0) *(float2*)(o0 + col) = v0;
                if (st1) *(float2*)(o1 + col) = v1;
            }
        }
        // ---- epilogue mt=1 ----
        {
            float* o0 = out + (size_t)e10 * 128;
            float* o1 = out + (size_t)e11 * 128;
            bool st0 = (e10 < E), st1 = (e11 < E);
            #pragma unroll
            for (int nt = 0; nt < 4; nt++) {
                int col = h * 32 + nt * 8 + q * 2;
                float2 v0, v1;
                v0.x = silu_f(c[1][nt][0] + pts1a[nt].x);
                v0.y = silu_f(c[1][nt][1] + pts1a[nt].y);
                v1.x = silu_f(c[1][nt][2] + pts1b[nt].x);
                v1.y = silu_f(c[1][nt][3] + pts1b[nt].y);
                if (st0) *(float2*)(o0 + col) = v0;
                if (st1) *(float2*)(o1 + col) = v1;
            }
        }

        t = tn; p ^= 1;
    }
}

extern "C" void kernel_launch(void* const* d_in, const int* in_sizes, int n_in,
                              void* d_out, int out_size) {
    const int*   Z    = (const int*)d_in[0];
    const int*   src  = (const int*)d_in[1];
    const int*   dst  = (const int*)d_in[2];
    const float* rbf  = (const float*)d_in[3];
    const float* d    = (const float*)d_in[4];
    const float* emb  = (const float*)d_in[5];
    const float* Wr   = (const float*)d_in[6];
    const float* brbf = (const float*)d_in[7];
    const float* Wd   = (const float*)d_in[8];
    const float* bd   = (const float*)d_in[9];
    int E = in_sizes[1];
    int nTiles = (E + 127) / 128;

    precompute_kernel<<<N_TYPES + 64, 256>>>(emb, Wd, bd);
    ptsum_kernel<<<N_TYPES * N_TYPES, 128>>>();

    cudaFuncSetAttribute(main_kernel, cudaFuncAttributeMaxDynamicSharedMemorySize, SMEM_BYTES);
    int dev = 0, nsm = 148;
    cudaGetDevice(&dev);
    cudaDeviceGetAttribute(&nsm, cudaDevAttrMultiProcessorCount, dev);

    main_kernel<<<nsm, 512, SMEM_BYTES>>>(Z, src, dst, rbf, d, Wr, brbf,
                                          (float*)d_out, E, nTiles);
}

// round 9
// speedup vs baseline: 2.1695x; 1.0348x over previous
#include <cuda_runtime.h>
#include <cstdint>

#define N_TYPES 95

// Precomputed constants (device globals: no allocation allowed)
__device__ float    g_PT[N_TYPES * 256];            // PT1 (with b_dense) | PT2
__device__ unsigned g_W3F[16384];                   // W3 tf32, mma B-fragment order
__device__ float    g_PTS[N_TYPES * N_TYPES * 128]; // PT1[zs]+PT2[zd] pair table (4.6MB)

// silu via tanh: x*sigmoid(x) = h + h*tanh(h), h = x/2.  1 MUFU instead of 2.
__device__ __forceinline__ float silu_f(float x) {
    float h = 0.5f * x, t;
    asm("tanh.approx.f32 %0, %1;" : "=f"(t) : "f"(h));
    return fmaf(h, t, h);
}
__device__ __forceinline__ unsigned to_tf32(float x) {
    unsigned u; asm("cvt.rna.tf32.f32 %0, %1;" : "=r"(u) : "f"(x)); return u;
}
__device__ __forceinline__ unsigned pack_bf16(float hi, float lo) {
    unsigned r; asm("cvt.rn.bf16x2.f32 %0, %1, %2;" : "=r"(r) : "f"(hi), "f"(lo)); return r;
}
__device__ __forceinline__ void mma_tf32(float c[4],
                                         unsigned a0, unsigned a1, unsigned a2, unsigned a3,
                                         unsigned b0, unsigned b1) {
    asm volatile(
        "mma.sync.aligned.m16n8k8.row.col.f32.tf32.tf32.f32 "
        "{%0,%1,%2,%3}, {%4,%5,%6,%7}, {%8,%9}, {%0,%1,%2,%3};"
        : "+f"(c[0]), "+f"(c[1]), "+f"(c[2]), "+f"(c[3])
        : "r"(a0), "r"(a1), "r"(a2), "r"(a3), "r"(b0), "r"(b1));
}

// ---------------------------------------------------------------------------
// Precompute 1: PT[95][256] + W3 fragments
// Fragment layout: uint4 index (k*8 + ntgp)*32 + lane holds, for lane (g,q):
//   .x = W3[col=2ntgp*8+g][k*8+q]      .y = W3[same col][k*8+q+4]
//   .z = W3[col=(2ntgp+1)*8+g][k*8+q]  .w = W3[same col][k*8+q+4]
// ---------------------------------------------------------------------------
__global__ void precompute_kernel(const float* __restrict__ emb,
                                  const float* __restrict__ Wd,
                                  const float* __restrict__ bd) {
    int b = blockIdx.x, t = threadIdx.x;
    if (b < N_TYPES) {
        __shared__ float er[128];
        if (t < 128) er[t] = emb[b * 128 + t];
        __syncthreads();
        int i = t & 127, half = t >> 7;
        const float4* w4 = (const float4*)(Wd + (size_t)i * 384 + half * 128);
        float acc = (half == 0) ? bd[i] : 0.0f;   // fold b_dense into PT1
        #pragma unroll
        for (int k4 = 0; k4 < 32; k4++) {
            float4 w = w4[k4];
            acc += er[k4*4+0]*w.x + er[k4*4+1]*w.y + er[k4*4+2]*w.z + er[k4*4+3]*w.w;
        }
        g_PT[b * 256 + half * 128 + i] = acc;
    } else {
        int idx  = (b - N_TYPES) * 256 + t;   // 0..16383
        int s    = idx & 3;
        int lane = (idx >> 2) & 31;
        int kgrp = idx >> 7;
        int k    = kgrp >> 3, ntgp = kgrp & 7;
        int ntg  = ntgp * 2 + (s >> 1);
        int bsel = s & 1;
        int col  = ntg * 8 + (lane >> 2);
        int kk   = k * 8 + (lane & 3) + bsel * 4;
        g_W3F[idx] = to_tf32(Wd[(size_t)col * 384 + 256 + kk]);
    }
}

// Precompute 2: pair-sum table PTS[zs*95+zd][i] = PT1[zs][i] + PT2[zd][i]
__global__ void ptsum_kernel() {
    int b = blockIdx.x;              // 0 .. 95*95-1
    int zs = b / N_TYPES, zd = b - zs * N_TYPES;
    int i = threadIdx.x;             // 0..127
    g_PTS[(size_t)b * 128 + i] = g_PT[zs * 256 + i] + g_PT[zd * 256 + 128 + i];
}

// ---------------------------------------------------------------------------
// Main fused kernel: 2 CTAs/SM x 256 threads, 64-edge tiles, cross-tile
// software pipeline, ONE barrier per tile. When one CTA parks at its barrier
// the co-resident CTA's warps fill the issue slots (bubble overlap).
// Phase B partition: warp w -> M-group mq=w>>2 (32 rows), col quarter h=w&3.
// ---------------------------------------------------------------------------
#define BF_WORDS 16384
#define HF_WORDS 4096               // one H buffer: 64 rows x 128 cols bf16
#define SMEM_WORDS (BF_WORDS + 2*HF_WORDS + 768 + 128)
#define SMEM_BYTES (SMEM_WORDS * 4) // 101,888 B  (2 CTAs fit in 228KB)

__global__ void __launch_bounds__(256, 2) main_kernel(
    const int* __restrict__ Z, const int* __restrict__ src, const int* __restrict__ dst,
    const float* __restrict__ rbf, const float* __restrict__ dvec,
    const float* __restrict__ Wr, const float* __restrict__ brbf,
    float* __restrict__ out, int E, int nTiles)
{
    extern __shared__ unsigned sm[];
    unsigned* BFs   = sm;
    uint2*    HF0   = (uint2*)(sm + BF_WORDS);
    uint2*    HF1   = HF0 + (HF_WORDS / 2);
    float*    Wr_s  = (float*)(sm + BF_WORDS + 2 * HF_WORDS);
    float*    brbf_s= Wr_s + 768;

    int tid = threadIdx.x;
    for (int i = tid; i < BF_WORDS; i += 256) BFs[i] = g_W3F[i];
    for (int i = tid; i < 768; i += 256) Wr_s[i] = Wr[i];
    if (tid < 128) brbf_s[tid] = brbf[tid];

    int lane = tid & 31, w = tid >> 5;
    int g = lane >> 2, q = lane & 3;
    int rgA = w & 3, kA = (w >> 2) * 8;   // phase A: row-group (0..3), k-range
    int rA0 = rgA * 16 + g;
    int mq = w >> 2, h = w & 3;           // phase B: 32-row group, 32-col quarter
    size_t envBase = (size_t)E * 128;
    const uint4* BF4 = (const uint4*)BFs;
    const float PIf = 3.14159265358979323846f;

    __syncthreads();   // Wr_s/brbf_s/BFs ready

    int t = blockIdx.x;
    int p = 0;
    if (t >= nTiles) return;

    // ---- prologue: A(t0) into HF0 ----
    {
        int basen = t * 64;
        int eA0 = min(basen + rA0, E - 1), eA1 = min(basen + rA0 + 8, E - 1);
        float rbA[6], rbB[6];
        #pragma unroll
        for (int j = 0; j < 6; j++) {
            rbA[j] = __ldg(rbf + (size_t)eA0 * 6 + j);
            rbB[j] = __ldg(rbf + (size_t)eA1 * 6 + j);
        }
        #pragma unroll
        for (int kk = 0; kk < 8; kk++) {
            int k = kA + kk, ca = 8 * k + q;
            const float* wA = Wr_s + ca * 6;
            float pa0 = brbf_s[ca],     pa1 = pa0;
            float pb0 = brbf_s[ca + 4], pb1 = pb0;
            #pragma unroll
            for (int j = 0; j < 6; j++) {
                float wa = wA[j], wb = wA[24 + j];
                pa0 += rbA[j] * wa;  pa1 += rbB[j] * wa;
                pb0 += rbA[j] * wb;  pb1 += rbB[j] * wb;
            }
            uint2 v;
            v.x = pack_bf16(silu_f(pa1), silu_f(pa0));
            v.y = pack_bf16(silu_f(pb1), silu_f(pb0));
            HF0[(rgA * 16 + k) * 32 + lane] = v;
        }
    }

    // ---- pipelined main loop: one barrier per tile ----
    while (t < nTiles) {
        __syncthreads();                       // HF[p] complete; prior reads done
        int base = t * 64;
        int tn = t + gridDim.x;
        uint2* HFr = p ? HF1 : HF0;            // B reads
        uint2* HFw = p ? HF0 : HF1;            // A writes

        // epilogue z-chain prefetch (long-latency, consumed after MMAs)
        int r0 = (2 * mq) * 16 + g;            // mt=0 base row
        int r1 = r0 + 16;                      // mt=1 base row
        int e00 = base + r0, e01 = e00 + 8;
        int e10 = base + r1, e11 = e10 + 8;
        int c00 = min(e00, E - 1), c01 = min(e01, E - 1);
        int c10 = min(e10, E - 1), c11 = min(e11, E - 1);
        int s00 = __ldg(src + c00), d00 = __ldg(dst + c00);
        int s01 = __ldg(src + c01), d01 = __ldg(dst + c01);
        int s10 = __ldg(src + c10), d10 = __ldg(dst + c10);
        int s11 = __ldg(src + c11), d11 = __ldg(dst + c11);

        // bessel / envelope branch for tile t: 128 threads, 3 sins each
        if (tid < 128) {
            int e = base + (tid >> 1);
            if (e < E) {
                int half3 = (tid & 1) * 3;
                float x = dvec[e] * 0.2f;
                float inv = 1.0f / x;
                float x2 = x*x, x4 = x2*x2, x5 = x4*x, x6 = x5*x, x7 = x6*x;
                float env = inv - 28.0f*x5 + 48.0f*x6 - 21.0f*x7;   // p = 6
                float s = env * inv;
                float* oo = out + envBase + (size_t)e * 6 + half3;
                #pragma unroll
                for (int n = 1; n <= 3; n++)
                    oo[n - 1] = s * __sinf(((float)(n + half3) * PIf) * x);
            }
        }

        const float* P00 = g_PTS + ((size_t)__ldg(Z + s00) * N_TYPES + __ldg(Z + d00)) * 128;
        const float* P01 = g_PTS + ((size_t)__ldg(Z + s01) * N_TYPES + __ldg(Z + d01)) * 128;
        const float* P10 = g_PTS + ((size_t)__ldg(Z + s10) * N_TYPES + __ldg(Z + d10)) * 128;
        const float* P11 = g_PTS + ((size_t)__ldg(Z + s11) * N_TYPES + __ldg(Z + d11)) * 128;

        // prefetch mt=0 pair-table values (hidden behind the MMA k-loop)
        float2 pts0a[4], pts0b[4];
        #pragma unroll
        for (int nt = 0; nt < 4; nt++) {
            int col = h * 32 + nt * 8 + q * 2;
            pts0a[nt] = __ldg((const float2*)(P00 + col));
            pts0b[nt] = __ldg((const float2*)(P01 + col));
        }

        // A(tn) inputs from global
        bool doA = (tn < nTiles);
        int basen = doA ? tn * 64 : 0;
        int eA0 = min(basen + rA0, E - 1), eA1 = min(basen + rA0 + 8, E - 1);
        float rbA[6], rbB[6];
        if (doA) {
            #pragma unroll
            for (int j = 0; j < 6; j++) {
                rbA[j] = __ldg(rbf + (size_t)eA0 * 6 + j);
                rbB[j] = __ldg(rbf + (size_t)eA1 * 6 + j);
            }
        }

        float c[2][4][4];
        #pragma unroll
        for (int mt = 0; mt < 2; mt++)
            #pragma unroll
            for (int nt = 0; nt < 4; nt++)
                { c[mt][nt][0]=0.f; c[mt][nt][1]=0.f; c[mt][nt][2]=0.f; c[mt][nt][3]=0.f; }

        // fused loop: 1 A-iter + 2 B-iters per step (mix FMA/MUFU with MMA/LDS)
        #pragma unroll 2
        for (int kk = 0; kk < 8; kk++) {
            if (doA) {
                int k = kA + kk, ca = 8 * k + q;
                const float* wA = Wr_s + ca * 6;
                float pa0 = brbf_s[ca],     pa1 = pa0;
                float pb0 = brbf_s[ca + 4], pb1 = pb0;
                #pragma unroll
                for (int j = 0; j < 6; j++) {
                    float wa = wA[j], wb = wA[24 + j];
                    pa0 += rbA[j] * wa;  pa1 += rbB[j] * wa;
                    pb0 += rbA[j] * wb;  pb1 += rbB[j] * wb;
                }
                uint2 v;
                v.x = pack_bf16(silu_f(pa1), silu_f(pa0));
                v.y = pack_bf16(silu_f(pb1), silu_f(pb0));
                HFw[(rgA * 16 + k) * 32 + lane] = v;
            }
            #pragma unroll
            for (int ks = 0; ks < 2; ks++) {
                int k = 2 * kk + ks;
                int bb = (k * 8 + h * 2) * 32 + lane;
                uint4 b0 = BF4[bb], b1 = BF4[bb + 32];
                uint2 Am0 = HFr[((2 * mq)     * 16 + k) * 32 + lane];
                uint2 Am1 = HFr[((2 * mq + 1) * 16 + k) * 32 + lane];
                unsigned a00 = Am0.x << 16, a01 = Am0.x & 0xFFFF0000u;
                unsigned a02 = Am0.y << 16, a03 = Am0.y & 0xFFFF0000u;
                unsigned a10 = Am1.x << 16, a11 = Am1.x & 0xFFFF0000u;
                unsigned a12 = Am1.y << 16, a13 = Am1.y & 0xFFFF0000u;
                mma_tf32(c[0][0], a00,a01,a02,a03, b0.x, b0.y);
                mma_tf32(c[0][1], a00,a01,a02,a03, b0.z, b0.w);
                mma_tf32(c[0][2], a00,a01,a02,a03, b1.x, b1.y);
                mma_tf32(c[0][3], a00,a01,a02,a03, b1.z, b1.w);
                mma_tf32(c[1][0], a10,a11,a12,a13, b0.x, b0.y);
                mma_tf32(c[1][1], a10,a11,a12,a13, b0.z, b0.w);
                mma_tf32(c[1][2], a10,a11,a12,a13, b1.x, b1.y);
                mma_tf32(c[1][3], a10,a11,a12,a13, b1.z, b1.w);
            }
        }

        // mt=1 pair-table loads issued now (hidden behind mt=0 epilogue)
        float2 pts1a[4], pts1b[4];
        #pragma unroll
        for (int nt = 0; nt < 4; nt++) {
            int col = h * 32 + nt * 8 + q * 2;
            pts1a[nt] = __ldg((const float2*)(P10 + col));
            pts1b[nt] = __ldg((const float2*)(P11 + col));
        }

        // ---- epilogue mt=0 ----
        {
            float* o0 = out + (size_t)e00 * 128;
            float* o1 = out + (size_t)e01 * 128;
            bool st0 = (e00 < E), st1 = (e01 < E);
            #pragma unroll
            for (int nt = 0; nt < 4; nt++) {
                int col = h * 32 + nt * 8 + q * 2;
                float2 v0, v1;
                v0.x = silu_f(c[0][nt][0] + pts0a[nt].x);
                v0.y = silu_f(c[0][nt][1] + pts0a[nt].y);
                v1.x = silu_f(c[0][nt][2] + pts0b[nt].x);
                v1.y = silu_f(c[0][nt][3] + pts0b[nt].y);
                if (st0) *(float2*)(o0 + col) = v0;
                if (st1) *(float2*)(o1 + col) = v1;
            }
        }
        // ---- epilogue mt=1 ----
        {
            float* o0 = out + (size_t)e10 * 128;
            float* o1 = out + (size_t)e11 * 128;
            bool st0 = (e10 < E), st1 = (e11 < E);
            #pragma unroll
            for (int nt = 0; nt < 4; nt++) {
                int col = h * 32 + nt * 8 + q * 2;
                float2 v0, v1;
                v0.x = silu_f(c[1][nt][0] + pts1a[nt].x);
                v0.y = silu_f(c[1][nt][1] + pts1a[nt].y);
                v1.x = silu_f(c[1][nt][2] + pts1b[nt].x);
                v1.y = silu_f(c[1][nt][3] + pts1b[nt].y);
                if (st0) *(float2*)(o0 + col) = v0;
                if (st1) *(float2*)(o1 + col) = v1;
            }
        }

        t = tn; p ^= 1;
    }
}

extern "C" void kernel_launch(void* const* d_in, const int* in_sizes, int n_in,
                              void* d_out, int out_size) {
    const int*   Z    = (const int*)d_in[0];
    const int*   src  = (const int*)d_in[1];
    const int*   dst  = (const int*)d_in[2];
    const float* rbf  = (const float*)d_in[3];
    const float* d    = (const float*)d_in[4];
    const float* emb  = (const float*)d_in[5];
    const float* Wr   = (const float*)d_in[6];
    const float* brbf = (const float*)d_in[7];
    const float* Wd   = (const float*)d_in[8];
    const float* bd   = (const float*)d_in[9];
    int E = in_sizes[1];
    int nTiles = (E + 63) / 64;

    precompute_kernel<<<N_TYPES + 64, 256>>>(emb, Wd, bd);
    ptsum_kernel<<<N_TYPES * N_TYPES, 128>>>();

    cudaFuncSetAttribute(main_kernel, cudaFuncAttributeMaxDynamicSharedMemorySize, SMEM_BYTES);
    int dev = 0, nsm = 148;
    cudaGetDevice(&dev);
    cudaDeviceGetAttribute(&nsm, cudaDevAttrMultiProcessorCount, dev);

    main_kernel<<<2 * nsm, 256, SMEM_BYTES>>>(Z, src, dst, rbf, d, Wr, brbf,
                                              (float*)d_out, E, nTiles);
}

// round 10
// speedup vs baseline: 2.4391x; 1.1243x over previous
#include <cuda_runtime.h>
#include <cstdint>

#define N_TYPES 95

// Precomputed constants (device globals: no allocation allowed)
__device__ float    g_PT[N_TYPES * 256];            // PT1 (with b_dense) | PT2
__device__ unsigned g_W3F[8192];                    // W3 bf16x2, m16n8k16 B-fragment order
__device__ float    g_PTS[N_TYPES * N_TYPES * 128]; // PT1[zs]+PT2[zd] pair table (4.6MB)

// silu via tanh: x*sigmoid(x) = h + h*tanh(h), h = x/2.  1 MUFU instead of 2.
__device__ __forceinline__ float silu_f(float x) {
    float h = 0.5f * x, t;
    asm("tanh.approx.f32 %0, %1;" : "=f"(t) : "f"(h));
    return fmaf(h, t, h);
}
__device__ __forceinline__ unsigned pack_bf16(float hi, float lo) {
    unsigned r; asm("cvt.rn.bf16x2.f32 %0, %1, %2;" : "=r"(r) : "f"(hi), "f"(lo)); return r;
}
// bf16 mma m16n8k16: A={a0..a3} (bf16x2 each), B={b0,b1}, C f32
__device__ __forceinline__ void mma_bf16(float c[4],
                                         unsigned a0, unsigned a1, unsigned a2, unsigned a3,
                                         unsigned b0, unsigned b1) {
    asm volatile(
        "mma.sync.aligned.m16n8k16.row.col.f32.bf16.bf16.f32 "
        "{%0,%1,%2,%3}, {%4,%5,%6,%7}, {%8,%9}, {%0,%1,%2,%3};"
        : "+f"(c[0]), "+f"(c[1]), "+f"(c[2]), "+f"(c[3])
        : "r"(a0), "r"(a1), "r"(a2), "r"(a3), "r"(b0), "r"(b1));
}

// ---------------------------------------------------------------------------
// Precompute 1: PT[95][256] + W3 bf16 fragments.
// BF4[(kc*8 + p)*32 + lane] (uint4), word s (0..3):
//   ntg = 2p + (s>>1), bsel = s&1, col = ntg*8 + (lane>>2),
//   k0 = kc*16 + 2*(lane&3) + bsel*8 ->  word = bf16x2{ W3[col][k0] lo, W3[col][k0+1] hi }
// ---------------------------------------------------------------------------
__global__ void precompute_kernel(const float* __restrict__ emb,
                                  const float* __restrict__ Wd,
                                  const float* __restrict__ bd) {
    int b = blockIdx.x, t = threadIdx.x;
    if (b < N_TYPES) {
        __shared__ float er[128];
        if (t < 128) er[t] = emb[b * 128 + t];
        __syncthreads();
        int i = t & 127, half = t >> 7;
        const float4* w4 = (const float4*)(Wd + (size_t)i * 384 + half * 128);
        float acc = (half == 0) ? bd[i] : 0.0f;   // fold b_dense into PT1
        #pragma unroll
        for (int k4 = 0; k4 < 32; k4++) {
            float4 w = w4[k4];
            acc += er[k4*4+0]*w.x + er[k4*4+1]*w.y + er[k4*4+2]*w.z + er[k4*4+3]*w.w;
        }
        g_PT[b * 256 + half * 128 + i] = acc;
    } else {
        int idx  = (b - N_TYPES) * 256 + t;   // 0..8191
        int s    = idx & 3;
        int lane = (idx >> 2) & 31;
        int p    = (idx >> 7) & 7;
        int kc   = (idx >> 10) & 7;
        int ntg  = 2 * p + (s >> 1);
        int bsel = s & 1;
        int g    = lane >> 2, q = lane & 3;
        int col  = ntg * 8 + g;
        int k0   = kc * 16 + 2 * q + bsel * 8;
        const float* wrow = Wd + (size_t)col * 384 + 256;
        g_W3F[idx] = pack_bf16(wrow[k0 + 1], wrow[k0]);
    }
}

// Precompute 2: pair-sum table PTS[zs*95+zd][i] = PT1[zs][i] + PT2[zd][i]
__global__ void ptsum_kernel() {
    int b = blockIdx.x;              // 0 .. 95*95-1
    int zs = b / N_TYPES, zd = b - zs * N_TYPES;
    int i = threadIdx.x;             // 0..127
    g_PTS[(size_t)b * 128 + i] = g_PT[zs * 256 + i] + g_PT[zd * 256 + 128 + i];
}

// ---------------------------------------------------------------------------
// Main fused kernel: 2 CTAs/SM x 256 threads, 64-edge tiles, cross-tile
// software pipeline, ONE barrier per tile.  bf16 m16n8k16 MMA:
// 8 k-chunks of 16; warp w -> M-group mq=w>>2 (32 rows), col quarter h=w&3.
// H fragments stored as ready-to-mma uint4 (one LDS.128 per m-tile per chunk).
// ---------------------------------------------------------------------------
#define BF_WORDS 8192               // W3 bf16 fragments (32 KB)
#define HF_WORDS 4096               // one H buffer: 64 rows x 128 k bf16 (16 KB)
#define SMEM_WORDS (BF_WORDS + 2*HF_WORDS + 768 + 128)
#define SMEM_BYTES (SMEM_WORDS * 4) // 69,120 B (2 CTAs fit easily)

__global__ void __launch_bounds__(256, 2) main_kernel(
    const int* __restrict__ Z, const int* __restrict__ src, const int* __restrict__ dst,
    const float* __restrict__ rbf, const float* __restrict__ dvec,
    const float* __restrict__ Wr, const float* __restrict__ brbf,
    float* __restrict__ out, int E, int nTiles)
{
    extern __shared__ unsigned sm[];
    unsigned* BFs   = sm;
    uint4*    HF0   = (uint4*)(sm + BF_WORDS);
    uint4*    HF1   = HF0 + (HF_WORDS / 4);
    float*    Wr_s  = (float*)(sm + BF_WORDS + 2 * HF_WORDS);
    float*    brbf_s= Wr_s + 768;

    int tid = threadIdx.x;
    for (int i = tid; i < BF_WORDS; i += 256) BFs[i] = g_W3F[i];
    for (int i = tid; i < 768; i += 256) Wr_s[i] = Wr[i];
    if (tid < 128) brbf_s[tid] = brbf[tid];

    int lane = tid & 31, w = tid >> 5;
    int g = lane >> 2, q = lane & 3;
    int rgA = w & 3, kcA = (w >> 2) * 4;  // phase A: row-group (0..3), chunk range
    int rA0 = rgA * 16 + g;
    int mq = w >> 2, h = w & 3;           // phase B: 32-row group, 32-col quarter
    size_t envBase = (size_t)E * 128;
    const uint4* BF4 = (const uint4*)BFs;
    const float PIf = 3.14159265358979323846f;

    __syncthreads();   // Wr_s/brbf_s/BFs ready

    int t = blockIdx.x;
    int p = 0;
    if (t >= nTiles) return;

    // ---- prologue: A(t0) into HF0 ----
    {
        int basen = t * 64;
        int eA0 = min(basen + rA0, E - 1), eA1 = min(basen + rA0 + 8, E - 1);
        float rbA[6], rbB[6];
        #pragma unroll
        for (int j = 0; j < 6; j++) {
            rbA[j] = __ldg(rbf + (size_t)eA0 * 6 + j);
            rbB[j] = __ldg(rbf + (size_t)eA1 * 6 + j);
        }
        #pragma unroll
        for (int kk = 0; kk < 4; kk++) {
            int kc = kcA + kk;
            int c0 = kc * 16 + 2 * q;
            const float* w0 = Wr_s + c0 * 6;
            float hA0 = brbf_s[c0],     hB0 = hA0;
            float hA1 = brbf_s[c0 + 1], hB1 = hA1;
            float hA2 = brbf_s[c0 + 8], hB2 = hA2;
            float hA3 = brbf_s[c0 + 9], hB3 = hA3;
            #pragma unroll
            for (int j = 0; j < 6; j++) {
                float w_0 = w0[j], w_1 = w0[6 + j], w_2 = w0[48 + j], w_3 = w0[54 + j];
                hA0 += rbA[j] * w_0;  hB0 += rbB[j] * w_0;
                hA1 += rbA[j] * w_1;  hB1 += rbB[j] * w_1;
                hA2 += rbA[j] * w_2;  hB2 += rbB[j] * w_2;
                hA3 += rbA[j] * w_3;  hB3 += rbB[j] * w_3;
            }
            uint4 v;
            v.x = pack_bf16(silu_f(hA1), silu_f(hA0));   // row g,   k c0..c0+1
            v.y = pack_bf16(silu_f(hB1), silu_f(hB0));   // row g+8, k c0..c0+1
            v.z = pack_bf16(silu_f(hA3), silu_f(hA2));   // row g,   k c0+8..c0+9
            v.w = pack_bf16(silu_f(hB3), silu_f(hB2));   // row g+8, k c0+8..c0+9
            HF0[(rgA * 8 + kc) * 32 + lane] = v;
        }
    }

    // ---- pipelined main loop: one barrier per tile ----
    while (t < nTiles) {
        __syncthreads();                       // HF[p] complete; prior reads done
        int base = t * 64;
        int tn = t + gridDim.x;
        uint4* HFr = p ? HF1 : HF0;            // B reads
        uint4* HFw = p ? HF0 : HF1;            // A writes

        // epilogue z-chain prefetch (long-latency, consumed after MMAs)
        int r0 = (2 * mq) * 16 + g;            // mt=0 base row
        int r1 = r0 + 16;                      // mt=1 base row
        int e00 = base + r0, e01 = e00 + 8;
        int e10 = base + r1, e11 = e10 + 8;
        int c00 = min(e00, E - 1), c01 = min(e01, E - 1);
        int c10 = min(e10, E - 1), c11 = min(e11, E - 1);
        int s00 = __ldg(src + c00), d00 = __ldg(dst + c00);
        int s01 = __ldg(src + c01), d01 = __ldg(dst + c01);
        int s10 = __ldg(src + c10), d10 = __ldg(dst + c10);
        int s11 = __ldg(src + c11), d11 = __ldg(dst + c11);

        // bessel / envelope branch for tile t: 128 threads, 3 sins each
        if (tid < 128) {
            int e = base + (tid >> 1);
            if (e < E) {
                int half3 = (tid & 1) * 3;
                float x = dvec[e] * 0.2f;
                float inv = 1.0f / x;
                float x2 = x*x, x4 = x2*x2, x5 = x4*x, x6 = x5*x, x7 = x6*x;
                float env = inv - 28.0f*x5 + 48.0f*x6 - 21.0f*x7;   // p = 6
                float s = env * inv;
                float* oo = out + envBase + (size_t)e * 6 + half3;
                #pragma unroll
                for (int n = 1; n <= 3; n++)
                    oo[n - 1] = s * __sinf(((float)(n + half3) * PIf) * x);
            }
        }

        const float* P00 = g_PTS + ((size_t)__ldg(Z + s00) * N_TYPES + __ldg(Z + d00)) * 128;
        const float* P01 = g_PTS + ((size_t)__ldg(Z + s01) * N_TYPES + __ldg(Z + d01)) * 128;
        const float* P10 = g_PTS + ((size_t)__ldg(Z + s10) * N_TYPES + __ldg(Z + d10)) * 128;
        const float* P11 = g_PTS + ((size_t)__ldg(Z + s11) * N_TYPES + __ldg(Z + d11)) * 128;

        // prefetch mt=0 pair-table values (hidden behind the MMA k-loop)
        float2 pts0a[4], pts0b[4];
        #pragma unroll
        for (int nt = 0; nt < 4; nt++) {
            int col = h * 32 + nt * 8 + q * 2;
            pts0a[nt] = __ldg((const float2*)(P00 + col));
            pts0b[nt] = __ldg((const float2*)(P01 + col));
        }

        // A(tn) inputs from global
        bool doA = (tn < nTiles);
        int basen = doA ? tn * 64 : 0;
        int eA0 = min(basen + rA0, E - 1), eA1 = min(basen + rA0 + 8, E - 1);
        float rbA[6], rbB[6];
        if (doA) {
            #pragma unroll
            for (int j = 0; j < 6; j++) {
                rbA[j] = __ldg(rbf + (size_t)eA0 * 6 + j);
                rbB[j] = __ldg(rbf + (size_t)eA1 * 6 + j);
            }
        }

        float c[2][4][4];
        #pragma unroll
        for (int mt = 0; mt < 2; mt++)
            #pragma unroll
            for (int nt = 0; nt < 4; nt++)
                { c[mt][nt][0]=0.f; c[mt][nt][1]=0.f; c[mt][nt][2]=0.f; c[mt][nt][3]=0.f; }

        // fused loop: 1 A-chunk + 2 B-chunks per step (mix FMA/MUFU with MMA/LDS)
        #pragma unroll 2
        for (int kk = 0; kk < 4; kk++) {
            if (doA) {
                int kc = kcA + kk;
                int c0 = kc * 16 + 2 * q;
                const float* w0 = Wr_s + c0 * 6;
                float hA0 = brbf_s[c0],     hB0 = hA0;
                float hA1 = brbf_s[c0 + 1], hB1 = hA1;
                float hA2 = brbf_s[c0 + 8], hB2 = hA2;
                float hA3 = brbf_s[c0 + 9], hB3 = hA3;
                #pragma unroll
                for (int j = 0; j < 6; j++) {
                    float w_0 = w0[j], w_1 = w0[6 + j], w_2 = w0[48 + j], w_3 = w0[54 + j];
                    hA0 += rbA[j] * w_0;  hB0 += rbB[j] * w_0;
                    hA1 += rbA[j] * w_1;  hB1 += rbB[j] * w_1;
                    hA2 += rbA[j] * w_2;  hB2 += rbB[j] * w_2;
                    hA3 += rbA[j] * w_3;  hB3 += rbB[j] * w_3;
                }
                uint4 v;
                v.x = pack_bf16(silu_f(hA1), silu_f(hA0));
                v.y = pack_bf16(silu_f(hB1), silu_f(hB0));
                v.z = pack_bf16(silu_f(hA3), silu_f(hA2));
                v.w = pack_bf16(silu_f(hB3), silu_f(hB2));
                HFw[(rgA * 8 + kc) * 32 + lane] = v;
            }
            #pragma unroll
            for (int ks = 0; ks < 2; ks++) {
                int kc = 2 * kk + ks;
                uint4 B0 = BF4[(kc * 8 + 2 * h)     * 32 + lane];
                uint4 B1 = BF4[(kc * 8 + 2 * h + 1) * 32 + lane];
                uint4 A0 = HFr[((2 * mq)     * 8 + kc) * 32 + lane];
                uint4 A1 = HFr[((2 * mq + 1) * 8 + kc) * 32 + lane];
                mma_bf16(c[0][0], A0.x, A0.y, A0.z, A0.w, B0.x, B0.y);
                mma_bf16(c[0][1], A0.x, A0.y, A0.z, A0.w, B0.z, B0.w);
                mma_bf16(c[0][2], A0.x, A0.y, A0.z, A0.w, B1.x, B1.y);
                mma_bf16(c[0][3], A0.x, A0.y, A0.z, A0.w, B1.z, B1.w);
                mma_bf16(c[1][0], A1.x, A1.y, A1.z, A1.w, B0.x, B0.y);
                mma_bf16(c[1][1], A1.x, A1.y, A1.z, A1.w, B0.z, B0.w);
                mma_bf16(c[1][2], A1.x, A1.y, A1.z, A1.w, B1.x, B1.y);
                mma_bf16(c[1][3], A1.x, A1.y, A1.z, A1.w, B1.z, B1.w);
            }
        }

        // mt=1 pair-table loads issued now (hidden behind mt=0 epilogue)
        float2 pts1a[4], pts1b[4];
        #pragma unroll
        for (int nt = 0; nt < 4; nt++) {
            int col = h * 32 + nt * 8 + q * 2;
            pts1a[nt] = __ldg((const float2*)(P10 + col));
            pts1b[nt] = __ldg((const float2*)(P11 + col));
        }

        // ---- epilogue mt=0 ----
        {
            float* o0 = out + (size_t)e00 * 128;
            float* o1 = out + (size_t)e01 * 128;
            bool st0 = (e00 < E), st1 = (e01 < E);
            #pragma unroll
            for (int nt = 0; nt < 4; nt++) {
                int col = h * 32 + nt * 8 + q * 2;
                float2 v0, v1;
                v0.x = silu_f(c[0][nt][0] + pts0a[nt].x);
                v0.y = silu_f(c[0][nt][1] + pts0a[nt].y);
                v1.x = silu_f(c[0][nt][2] + pts0b[nt].x);
                v1.y = silu_f(c[0][nt][3] + pts0b[nt].y);
                if (st0) *(float2*)(o0 + col) = v0;
                if (st1) *(float2*)(o1 + col) = v1;
            }
        }
        // ---- epilogue mt=1 ----
        {
            float* o0 = out + (size_t)e10 * 128;
            float* o1 = out + (size_t)e11 * 128;
            bool st0 = (e10 < E), st1 = (e11 < E);
            #pragma unroll
            for (int nt = 0; nt < 4; nt++) {
                int col = h * 32 + nt * 8 + q * 2;
                float2 v0, v1;
                v0.x = silu_f(c[1][nt][0] + pts1a[nt].x);
                v0.y = silu_f(c[1][nt][1] + pts1a[nt].y);
                v1.x = silu_f(c[1][nt][2] + pts1b[nt].x);
                v1.y = silu_f(c[1][nt][3] + pts1b[nt].y);
                if (st0) *(float2*)(o0 + col) = v0;
                if (st1) *(float2*)(o1 + col) = v1;
            }
        }

        t = tn; p ^= 1;
    }
}

extern "C" void kernel_launch(void* const* d_in, const int* in_sizes, int n_in,
                              void* d_out, int out_size) {
    const int*   Z    = (const int*)d_in[0];
    const int*   src  = (const int*)d_in[1];
    const int*   dst  = (const int*)d_in[2];
    const float* rbf  = (const float*)d_in[3];
    const float* d    = (const float*)d_in[4];
    const float* emb  = (const float*)d_in[5];
    const float* Wr   = (const float*)d_in[6];
    const float* brbf = (const float*)d_in[7];
    const float* Wd   = (const float*)d_in[8];
    const float* bd   = (const float*)d_in[9];
    int E = in_sizes[1];
    int nTiles = (E + 63) / 64;

    precompute_kernel<<<N_TYPES + 32, 256>>>(emb, Wd, bd);
    ptsum_kernel<<<N_TYPES * N_TYPES, 128>>>();

    cudaFuncSetAttribute(main_kernel, cudaFuncAttributeMaxDynamicSharedMemorySize, SMEM_BYTES);
    int dev = 0, nsm = 148;
    cudaGetDevice(&dev);
    cudaDeviceGetAttribute(&nsm, cudaDevAttrMultiProcessorCount, dev);

    main_kernel<<<2 * nsm, 256, SMEM_BYTES>>>(Z, src, dst, rbf, d, Wr, brbf,
                                              (float*)d_out, E, nTiles);
}

// round 11
// speedup vs baseline: 2.6815x; 1.0994x over previous
#include <cuda_runtime.h>
#include <cstdint>

#define N_TYPES 95

// Precomputed constants (device globals: no allocation allowed)
__device__ float    g_PT[N_TYPES * 256];            // PT1 (with b_dense) | PT2
__device__ unsigned g_W3F[8192];                    // W3 bf16x2, m16n8k16 B-fragment order
__device__ float    g_PTS[N_TYPES * N_TYPES * 128]; // PT1[zs]+PT2[zd] pair table (4.6MB)

// silu via tanh: x*sigmoid(x) = h + h*tanh(h), h = x/2.  1 MUFU instead of 2.
__device__ __forceinline__ float silu_f(float x) {
    float h = 0.5f * x, t;
    asm("tanh.approx.f32 %0, %1;" : "=f"(t) : "f"(h));
    return fmaf(h, t, h);
}
__device__ __forceinline__ unsigned pack_bf16(float hi, float lo) {
    unsigned r; asm("cvt.rn.bf16x2.f32 %0, %1, %2;" : "=r"(r) : "f"(hi), "f"(lo)); return r;
}
// bf16 mma m16n8k16: A={a0..a3} (bf16x2 each), B={b0,b1}, C f32
__device__ __forceinline__ void mma_bf16(float c[4],
                                         unsigned a0, unsigned a1, unsigned a2, unsigned a3,
                                         unsigned b0, unsigned b1) {
    asm volatile(
        "mma.sync.aligned.m16n8k16.row.col.f32.bf16.bf16.f32 "
        "{%0,%1,%2,%3}, {%4,%5,%6,%7}, {%8,%9}, {%0,%1,%2,%3};"
        : "+f"(c[0]), "+f"(c[1]), "+f"(c[2]), "+f"(c[3])
        : "r"(a0), "r"(a1), "r"(a2), "r"(a3), "r"(b0), "r"(b1));
}

// ---------------------------------------------------------------------------
// Precompute 1: PT[95][256] + W3 bf16 fragments (same layout as R10).
// BF4[(kc*8 + p)*32 + lane] (uint4), word s (0..3):
//   ntg = 2p + (s>>1), bsel = s&1, col = ntg*8 + (lane>>2),
//   k0 = kc*16 + 2*(lane&3) + bsel*8 ->  word = bf16x2{ W3[col][k0], W3[col][k0+1] }
// ---------------------------------------------------------------------------
__global__ void precompute_kernel(const float* __restrict__ emb,
                                  const float* __restrict__ Wd,
                                  const float* __restrict__ bd) {
    int b = blockIdx.x, t = threadIdx.x;
    if (b < N_TYPES) {
        __shared__ float er[128];
        if (t < 128) er[t] = emb[b * 128 + t];
        __syncthreads();
        int i = t & 127, half = t >> 7;
        const float4* w4 = (const float4*)(Wd + (size_t)i * 384 + half * 128);
        float acc = (half == 0) ? bd[i] : 0.0f;   // fold b_dense into PT1
        #pragma unroll
        for (int k4 = 0; k4 < 32; k4++) {
            float4 w = w4[k4];
            acc += er[k4*4+0]*w.x + er[k4*4+1]*w.y + er[k4*4+2]*w.z + er[k4*4+3]*w.w;
        }
        g_PT[b * 256 + half * 128 + i] = acc;
    } else {
        int idx  = (b - N_TYPES) * 256 + t;   // 0..8191
        int s    = idx & 3;
        int lane = (idx >> 2) & 31;
        int p    = (idx >> 7) & 7;
        int kc   = (idx >> 10) & 7;
        int ntg  = 2 * p + (s >> 1);
        int bsel = s & 1;
        int g    = lane >> 2, q = lane & 3;
        int col  = ntg * 8 + g;
        int k0   = kc * 16 + 2 * q + bsel * 8;
        const float* wrow = Wd + (size_t)col * 384 + 256;
        g_W3F[idx] = pack_bf16(wrow[k0 + 1], wrow[k0]);
    }
}

// Precompute 2: pair-sum table, grid-stride float4 (bandwidth-shaped)
__global__ void ptsum_kernel() {
    int stride = gridDim.x * blockDim.x;
    for (int i = blockIdx.x * blockDim.x + threadIdx.x;
         i < N_TYPES * N_TYPES * 32; i += stride) {
        int pair = i >> 5, c4 = (i & 31) * 4;
        int zs = pair / N_TYPES, zd = pair - zs * N_TYPES;
        float4 a = *(const float4*)(g_PT + zs * 256 + c4);
        float4 b = *(const float4*)(g_PT + zd * 256 + 128 + c4);
        float4 v = make_float4(a.x + b.x, a.y + b.y, a.z + b.z, a.w + b.w);
        *(float4*)(g_PTS + (size_t)pair * 128 + c4) = v;
    }
}

// ---------------------------------------------------------------------------
// Main fused kernel: 2 CTAs/SM x 256 threads, 64-edge tiles, cross-tile
// software pipeline, ONE barrier per tile.
// NEW vs R10: W3 B-fragments are REGISTER-RESIDENT (loop-invariant, 64 regs
// per warp loaded once from g_W3F) -> zero B LDS, no BF smem (SMEM 69->36KB,
// bigger L1D carveout for PTS). Phase A un-fused from the MMA loop and pts
// loads inlined to stay under the 128-reg cap; the co-resident CTA provides
// pipe mixing.
// ---------------------------------------------------------------------------
#define HF_WORDS 4096               // one H buffer: 64 rows x 128 k bf16 (16 KB)
#define SMEM_WORDS (2*HF_WORDS + 768 + 128)
#define SMEM_BYTES (SMEM_WORDS * 4) // 36,224 B

__global__ void __launch_bounds__(256, 2) main_kernel(
    const int* __restrict__ Z, const int* __restrict__ src, const int* __restrict__ dst,
    const float* __restrict__ rbf, const float* __restrict__ dvec,
    const float* __restrict__ Wr, const float* __restrict__ brbf,
    float* __restrict__ out, int E, int nTiles)
{
    extern __shared__ unsigned sm[];
    uint4*    HF0   = (uint4*)sm;
    uint4*    HF1   = HF0 + (HF_WORDS / 4);
    float*    Wr_s  = (float*)(sm + 2 * HF_WORDS);
    float*    brbf_s= Wr_s + 768;

    int tid = threadIdx.x;
    for (int i = tid; i < 768; i += 256) Wr_s[i] = Wr[i];
    if (tid < 128) brbf_s[tid] = brbf[tid];

    int lane = tid & 31, w = tid >> 5;
    int g = lane >> 2, q = lane & 3;
    int rgA = w & 3, kcA = (w >> 2) * 4;  // phase A: row-group (0..3), chunk range
    int rA0 = rgA * 16 + g;
    int mq = w >> 2, h = w & 3;           // phase B: 32-row group, 32-col quarter
    size_t envBase = (size_t)E * 128;
    const float PIf = 3.14159265358979323846f;

    // W3 B-fragments: register-resident for this warp's column quarter
    uint4 BR0[8], BR1[8];
    {
        const uint4* GW = (const uint4*)g_W3F;
        #pragma unroll
        for (int kc = 0; kc < 8; kc++) {
            BR0[kc] = __ldg(GW + (kc * 8 + 2 * h)     * 32 + lane);
            BR1[kc] = __ldg(GW + (kc * 8 + 2 * h + 1) * 32 + lane);
        }
    }

    __syncthreads();   // Wr_s/brbf_s ready

    int t = blockIdx.x;
    int p = 0;
    if (t >= nTiles) return;

    // ---- prologue: A(t0) into HF0 ----
    {
        int basen = t * 64;
        int eA0 = min(basen + rA0, E - 1), eA1 = min(basen + rA0 + 8, E - 1);
        float rbA[6], rbB[6];
        #pragma unroll
        for (int j = 0; j < 6; j++) {
            rbA[j] = __ldg(rbf + (size_t)eA0 * 6 + j);
            rbB[j] = __ldg(rbf + (size_t)eA1 * 6 + j);
        }
        #pragma unroll
        for (int kk = 0; kk < 4; kk++) {
            int kc = kcA + kk;
            int c0 = kc * 16 + 2 * q;
            const float* w0 = Wr_s + c0 * 6;
            float hA0 = brbf_s[c0],     hB0 = hA0;
            float hA1 = brbf_s[c0 + 1], hB1 = hA1;
            float hA2 = brbf_s[c0 + 8], hB2 = hA2;
            float hA3 = brbf_s[c0 + 9], hB3 = hA3;
            #pragma unroll
            for (int j = 0; j < 6; j++) {
                float w_0 = w0[j], w_1 = w0[6 + j], w_2 = w0[48 + j], w_3 = w0[54 + j];
                hA0 += rbA[j] * w_0;  hB0 += rbB[j] * w_0;
                hA1 += rbA[j] * w_1;  hB1 += rbB[j] * w_1;
                hA2 += rbA[j] * w_2;  hB2 += rbB[j] * w_2;
                hA3 += rbA[j] * w_3;  hB3 += rbB[j] * w_3;
            }
            uint4 v;
            v.x = pack_bf16(silu_f(hA1), silu_f(hA0));   // row g,   k c0..c0+1
            v.y = pack_bf16(silu_f(hB1), silu_f(hB0));   // row g+8, k c0..c0+1
            v.z = pack_bf16(silu_f(hA3), silu_f(hA2));   // row g,   k c0+8..c0+9
            v.w = pack_bf16(silu_f(hB3), silu_f(hB2));   // row g+8, k c0+8..c0+9
            HF0[(rgA * 8 + kc) * 32 + lane] = v;
        }
    }

    // ---- pipelined main loop: one barrier per tile ----
    while (t < nTiles) {
        __syncthreads();                       // HF[p] complete; prior reads done
        int base = t * 64;
        int tn = t + gridDim.x;
        uint4* HFr = p ? HF1 : HF0;            // B reads
        uint4* HFw = p ? HF0 : HF1;            // A writes

        // epilogue z-chain prefetch (long-latency, consumed after MMAs)
        int r0 = (2 * mq) * 16 + g;            // mt=0 base row
        int r1 = r0 + 16;                      // mt=1 base row
        int e00 = base + r0, e01 = e00 + 8;
        int e10 = base + r1, e11 = e10 + 8;
        int c00 = min(e00, E - 1), c01 = min(e01, E - 1);
        int c10 = min(e10, E - 1), c11 = min(e11, E - 1);
        int s00 = __ldg(src + c00), d00 = __ldg(dst + c00);
        int s01 = __ldg(src + c01), d01 = __ldg(dst + c01);
        int s10 = __ldg(src + c10), d10 = __ldg(dst + c10);
        int s11 = __ldg(src + c11), d11 = __ldg(dst + c11);

        // bessel / envelope branch for tile t: 128 threads, 3 sins each
        if (tid < 128) {
            int e = base + (tid >> 1);
            if (e < E) {
                int half3 = (tid & 1) * 3;
                float x = dvec[e] * 0.2f;
                float inv = 1.0f / x;
                float x2 = x*x, x4 = x2*x2, x5 = x4*x, x6 = x5*x, x7 = x6*x;
                float env = inv - 28.0f*x5 + 48.0f*x6 - 21.0f*x7;   // p = 6
                float s = env * inv;
                float* oo = out + envBase + (size_t)e * 6 + half3;
                #pragma unroll
                for (int n = 1; n <= 3; n++)
                    oo[n - 1] = s * __sinf(((float)(n + half3) * PIf) * x);
            }
        }

        const float* P00 = g_PTS + ((size_t)__ldg(Z + s00) * N_TYPES + __ldg(Z + d00)) * 128;
        const float* P01 = g_PTS + ((size_t)__ldg(Z + s01) * N_TYPES + __ldg(Z + d01)) * 128;
        const float* P10 = g_PTS + ((size_t)__ldg(Z + s10) * N_TYPES + __ldg(Z + d10)) * 128;
        const float* P11 = g_PTS + ((size_t)__ldg(Z + s11) * N_TYPES + __ldg(Z + d11)) * 128;

        // ---- phase A(tn) -> HFw (un-fused; co-resident CTA mixes pipes) ----
        if (tn < nTiles) {
            int basen = tn * 64;
            int eA0 = min(basen + rA0, E - 1), eA1 = min(basen + rA0 + 8, E - 1);
            float rbA[6], rbB[6];
            #pragma unroll
            for (int j = 0; j < 6; j++) {
                rbA[j] = __ldg(rbf + (size_t)eA0 * 6 + j);
                rbB[j] = __ldg(rbf + (size_t)eA1 * 6 + j);
            }
            #pragma unroll 2
            for (int kk = 0; kk < 4; kk++) {
                int kc = kcA + kk;
                int c0 = kc * 16 + 2 * q;
                const float* w0 = Wr_s + c0 * 6;
                float hA0 = brbf_s[c0],     hB0 = hA0;
                float hA1 = brbf_s[c0 + 1], hB1 = hA1;
                float hA2 = brbf_s[c0 + 8], hB2 = hA2;
                float hA3 = brbf_s[c0 + 9], hB3 = hA3;
                #pragma unroll
                for (int j = 0; j < 6; j++) {
                    float w_0 = w0[j], w_1 = w0[6 + j], w_2 = w0[48 + j], w_3 = w0[54 + j];
                    hA0 += rbA[j] * w_0;  hB0 += rbB[j] * w_0;
                    hA1 += rbA[j] * w_1;  hB1 += rbB[j] * w_1;
                    hA2 += rbA[j] * w_2;  hB2 += rbB[j] * w_2;
                    hA3 += rbA[j] * w_3;  hB3 += rbB[j] * w_3;
                }
                uint4 v;
                v.x = pack_bf16(silu_f(hA1), silu_f(hA0));
                v.y = pack_bf16(silu_f(hB1), silu_f(hB0));
                v.z = pack_bf16(silu_f(hA3), silu_f(hA2));
                v.w = pack_bf16(silu_f(hB3), silu_f(hB2));
                HFw[(rgA * 8 + kc) * 32 + lane] = v;
            }
        }

        // ---- MMA loop: A via LDS.128, B from registers ----
        float c[2][4][4];
        #pragma unroll
        for (int mt = 0; mt < 2; mt++)
            #pragma unroll
            for (int nt = 0; nt < 4; nt++)
                { c[mt][nt][0]=0.f; c[mt][nt][1]=0.f; c[mt][nt][2]=0.f; c[mt][nt][3]=0.f; }

        #pragma unroll
        for (int kc = 0; kc < 8; kc++) {
            uint4 A0 = HFr[((2 * mq)     * 8 + kc) * 32 + lane];
            uint4 A1 = HFr[((2 * mq + 1) * 8 + kc) * 32 + lane];
            uint4 B0 = BR0[kc], B1 = BR1[kc];
            mma_bf16(c[0][0], A0.x, A0.y, A0.z, A0.w, B0.x, B0.y);
            mma_bf16(c[0][1], A0.x, A0.y, A0.z, A0.w, B0.z, B0.w);
            mma_bf16(c[0][2], A0.x, A0.y, A0.z, A0.w, B1.x, B1.y);
            mma_bf16(c[0][3], A0.x, A0.y, A0.z, A0.w, B1.z, B1.w);
            mma_bf16(c[1][0], A1.x, A1.y, A1.z, A1.w, B0.x, B0.y);
            mma_bf16(c[1][1], A1.x, A1.y, A1.z, A1.w, B0.z, B0.w);
            mma_bf16(c[1][2], A1.x, A1.y, A1.z, A1.w, B1.x, B1.y);
            mma_bf16(c[1][3], A1.x, A1.y, A1.z, A1.w, B1.z, B1.w);
        }

        // ---- epilogue mt=0 (pts loaded inline; L1 carveout is large now) ----
        {
            float* o0 = out + (size_t)e00 * 128;
            float* o1 = out + (size_t)e01 * 128;
            bool st0 = (e00 < E), st1 = (e01 < E);
            #pragma unroll
            for (int nt = 0; nt < 4; nt++) {
                int col = h * 32 + nt * 8 + q * 2;
                float2 pa = __ldg((const float2*)(P00 + col));
                float2 pb = __ldg((const float2*)(P01 + col));
                float2 v0, v1;
                v0.x = silu_f(c[0][nt][0] + pa.x);
                v0.y = silu_f(c[0][nt][1] + pa.y);
                v1.x = silu_f(c[0][nt][2] + pb.x);
                v1.y = silu_f(c[0][nt][3] + pb.y);
                if (st0) *(float2*)(o0 + col) = v0;
                if (st1) *(float2*)(o1 + col) = v1;
            }
        }
        // ---- epilogue mt=1 ----
        {
            float* o0 = out + (size_t)e10 * 128;
            float* o1 = out + (size_t)e11 * 128;
            bool st0 = (e10 < E), st1 = (e11 < E);
            #pragma unroll
            for (int nt = 0; nt < 4; nt++) {
                int col = h * 32 + nt * 8 + q * 2;
                float2 pa = __ldg((const float2*)(P10 + col));
                float2 pb = __ldg((const float2*)(P11 + col));
                float2 v0, v1;
                v0.x = silu_f(c[1][nt][0] + pa.x);
                v0.y = silu_f(c[1][nt][1] + pa.y);
                v1.x = silu_f(c[1][nt][2] + pb.x);
                v1.y = silu_f(c[1][nt][3] + pb.y);
                if (st0) *(float2*)(o0 + col) = v0;
                if (st1) *(float2*)(o1 + col) = v1;
            }
        }

        t = tn; p ^= 1;
    }
}

extern "C" void kernel_launch(void* const* d_in, const int* in_sizes, int n_in,
                              void* d_out, int out_size) {
    const int*   Z    = (const int*)d_in[0];
    const int*   src  = (const int*)d_in[1];
    const int*   dst  = (const int*)d_in[2];
    const float* rbf  = (const float*)d_in[3];
    const float* d    = (const float*)d_in[4];
    const float* emb  = (const float*)d_in[5];
    const float* Wr   = (const float*)d_in[6];
    const float* brbf = (const float*)d_in[7];
    const float* Wd   = (const float*)d_in[8];
    const float* bd   = (const float*)d_in[9];
    int E = in_sizes[1];
    int nTiles = (E + 63) / 64;

    precompute_kernel<<<N_TYPES + 32, 256>>>(emb, Wd, bd);
    ptsum_kernel<<<1184, 256>>>();

    cudaFuncSetAttribute(main_kernel, cudaFuncAttributeMaxDynamicSharedMemorySize, SMEM_BYTES);
    int dev = 0, nsm = 148;
    cudaGetDevice(&dev);
    cudaDeviceGetAttribute(&nsm, cudaDevAttrMultiProcessorCount, dev);

    main_kernel<<<2 * nsm, 256, SMEM_BYTES>>>(Z, src, dst, rbf, d, Wr, brbf,
                                              (float*)d_out, E, nTiles);
}